// round 12
// baseline (speedup 1.0000x reference)
#include <cuda_runtime.h>
#include <cuda_fp16.h>
#include <cstdint>
#include <math.h>

// Problem dims
#define B_    32
#define E_    64
#define R_    36
#define D_    512
#define DT_   768
#define DI_   2048
#define TROWS 2048   // B*E
#define IROWS 1152   // B*R
#define IROWS_P 1280 // padded to multiple of 256 for BM=256
#define SHI_S 516

// fp16 2-term split: A = [hi|lo] (width 2K), B = hi only (width K), virtual K = 2K
#define LDAT  (2*DT_)   // 1536
#define LDAI  (2*DI_)   // 4096
#define LDAD  (2*D_)    // 1024

// ---------------- scratch (device globals; .bss zero-initialized) ----------------
__device__ __align__(128) float g_T  [TROWS*D_];
__device__ __align__(128) float g_T2 [TROWS*D_];
__device__ __align__(128) float g_I  [IROWS_P*D_];
__device__ __align__(128) float g_I2 [IROWS_P*D_];
__device__ __align__(128) float g_I3 [IROWS_P*D_];
__device__ __align__(128) float g_I4 [IROWS_P*D_];
__device__ __align__(128) float g_HT [TROWS*D_];
__device__ __align__(128) float g_HT2[TROWS*D_];
__device__ __align__(128) float g_HI [IROWS_P*D_];
__device__ __align__(128) float g_HI2[IROWS_P*D_];
__device__ __align__(128) float g_tep[8*TROWS];
__device__ __align__(128) float g_urp[8*IROWS_P];

__device__ __align__(128) __half g_At [TROWS*LDAT];
__device__ __align__(128) __half g_Ai [IROWS_P*LDAI];   // rows >=1152 stay zero
__device__ __align__(128) __half g_AT2[TROWS*LDAD];
__device__ __align__(128) __half g_AI2[IROWS_P*LDAD];   // rows >=1152 stay zero
__device__ __align__(128) __half g_Bt [D_*DT_];
__device__ __align__(128) __half g_Bi [D_*DI_];
__device__ __align__(128) __half g_B1t[D_*D_];
__device__ __align__(128) __half g_B1i[D_*D_];

// ---------------- helpers ----------------
static __device__ __forceinline__ uint32_t smem_to_u32(const void* p){
    uint32_t a;
    asm("{ .reg .u64 t; cvta.to.shared.u64 t, %1; cvt.u32.u64 %0, t; }" : "=r"(a) : "l"(p));
    return a;
}

#define CP_ASYNC16(smad, gptr) \
    asm volatile("cp.async.ca.shared.global [%0], [%1], 16;" :: "r"(smad), "l"(gptr))
#define CP_COMMIT() asm volatile("cp.async.commit_group;" ::: "memory")
#define CP_WAIT3()  asm volatile("cp.async.wait_group 3;" ::: "memory")

#define LDSM_X4(r0,r1,r2,r3, addr) \
    asm volatile("ldmatrix.sync.aligned.m8n8.x4.shared.b16 {%0,%1,%2,%3}, [%4];" \
        : "=r"(r0), "=r"(r1), "=r"(r2), "=r"(r3) : "r"(addr))

static __device__ __forceinline__ void mma16816(float* c, const uint32_t* a, const uint32_t* b){
    asm volatile(
        "mma.sync.aligned.m16n8k16.row.col.f32.f16.f16.f32 "
        "{%0,%1,%2,%3}, {%4,%5,%6,%7}, {%8,%9}, {%0,%1,%2,%3};"
        : "+f"(c[0]), "+f"(c[1]), "+f"(c[2]), "+f"(c[3])
        : "r"(a[0]), "r"(a[1]), "r"(a[2]), "r"(a[3]), "r"(b[0]), "r"(b[1]));
}

static __device__ __forceinline__ void split_fp16(float x, __half& h, __half& l){
    h = __float2half_rn(x);
    l = __float2half_rn(x - __half2float(h));
}

// ---------------- merged conversion kernel ----------------
__global__ __launch_bounds__(256) void conv_all_k(const float* __restrict__ W_text,
                                                  const float* __restrict__ W_img,
                                                  const float* __restrict__ W1,
                                                  const float* __restrict__ text,
                                                  const float* __restrict__ image)
{
    __shared__ float t[32][33];
    int bx = blockIdx.x;
    if (bx < 1920) {
        const float* src; __half* dst; int K, idx;
        if      (bx < 384)  { src = W_text;       dst = g_Bt;  K = DT_; idx = bx; }
        else if (bx < 1408) { src = W_img;        dst = g_Bi;  K = DI_; idx = bx - 384; }
        else if (bx < 1664) { src = W1;           dst = g_B1t; K = D_;  idx = bx - 1408; }
        else                { src = W1 + D_ * D_; dst = g_B1i; K = D_;  idx = bx - 1664; }
        int kblocks = K / 32;
        int kb = (idx % kblocks) * 32, nb = (idx / kblocks) * 32;
        int tx = threadIdx.x & 31, ty = threadIdx.x >> 5;
        #pragma unroll
        for (int j = 0; j < 4; ++j)
            t[ty + 8*j][tx] = src[(size_t)(kb + ty + 8*j) * 512 + nb + tx];
        __syncthreads();
        #pragma unroll
        for (int j = 0; j < 4; ++j) {
            int n = nb + ty + 8*j, k = kb + tx;
            dst[(size_t)n * K + k] = __float2half_rn(t[tx][ty + 8*j]);
        }
    } else {
        int gi = (bx - 1920) * 256 + threadIdx.x;
        const float* src; __half* dst; int K, e;
        if (gi < TROWS * DT_) { src = text;  dst = g_At; K = DT_; e = gi; }
        else                  { src = image; dst = g_Ai; K = DI_; e = gi - TROWS * DT_; }
        int m = e / K, k = e - m * K;
        float x = src[e];
        __half h, l; split_fp16(x, h, l);
        __half* row = dst + (size_t)m * 2 * K;
        row[k] = h; row[K + k] = l;
    }
}

// ---------------- mma.sync GEMM: BM=256, BN=128, BK=32, 512 threads, 4-stage cp.async ----------------
struct Job {
    const __half* A;          // [M][lda] = [hi|lo], virtual K = lda
    const __half* B;          // [512][ldb] hi-only; virtual k wraps at ldb
    const float* bias;
    float* C;                 // [M][512]
    const float* w2;          // if non-null: fuse per-row dot C.w2 -> dotp
    float* dotp;              // [8][mrows] (split*4 + nblock)
    int lda, ldb;
    int aoff;                 // virtual-k start
    int NC;                   // chunks of 32
    int mrows;                // dotp row pitch
    int relu, hasbias;
};
struct JobPack { Job j[6]; int hi[6]; };

#define ROWB    80
#define TILE_A  20480          // 256 rows * 80B
#define STAGE_B 30720          // A(256) + B(128) rows
#define STAGES  4
#define SM_TOT  (STAGES*STAGE_B)   // 122880

__global__ __launch_bounds__(512, 1) void mma_gemm3(JobPack P)
{
    extern __shared__ __align__(128) char sm[];
    const uint32_t smb = smem_to_u32(sm);
    const int tid = threadIdx.x;
    const int wid = tid >> 5, lane = tid & 31;

    int bx = (int)blockIdx.x;
    int jx = 0;
    #pragma unroll
    for (int k = 0; k < 5; ++k) jx += (bx >= P.hi[k]);
    Job jb = P.j[jx];
    int rb = bx - (jx ? P.hi[jx-1] : 0);

    const int m0 = (rb >> 2) * 256, n0 = (rb & 3) * 128;
    const int lda = jb.lda, ldb = jb.ldb, NC = jb.NC, aoff = jb.aoff;

    const int wm = (wid >> 2) * 64;   // 0/64/128/192
    const int wn = (wid & 3) * 32;    // 0/32/64/96

    const int cRow = tid >> 2, cCol = tid & 3;   // cRow 0..127

    float acc[4][4][4];
    #pragma unroll
    for (int i = 0; i < 4; ++i)
        #pragma unroll
        for (int j = 0; j < 4; ++j)
            #pragma unroll
            for (int q = 0; q < 4; ++q) acc[i][j][q] = 0.f;

    const __half* gAb  = jb.A + (size_t)(m0 + cRow) * lda + cCol * 8;
    const __half* gAb2 = jb.A + (size_t)(m0 + cRow + 128) * lda + cCol * 8;
    const __half* gBb  = jb.B + (size_t)(n0 + cRow) * ldb + cCol * 8;
    const uint32_t sOffA  = (uint32_t)cRow * ROWB + cCol * 16;
    const uint32_t sOffA2 = (uint32_t)(cRow + 128) * ROWB + cCol * 16;
    const uint32_t sOffB  = TILE_A + (uint32_t)cRow * ROWB + cCol * 16;

    auto issue = [&](int chunk){
        if (chunk < NC) {
            const uint32_t sS = smb + (chunk & (STAGES-1)) * STAGE_B;
            int vk = aoff + chunk * 32;          // A index (virtual = stored)
            int bk = vk >= ldb ? vk - ldb : vk;  // B wraps onto hi
            CP_ASYNC16(sS + sOffA,  gAb  + vk);
            CP_ASYNC16(sS + sOffA2, gAb2 + vk);
            CP_ASYNC16(sS + sOffB,  gBb  + bk);
        }
        CP_COMMIT();
    };

    issue(0); issue(1); issue(2);

    const uint32_t aFragOff = (uint32_t)(wm + (lane & 15)) * ROWB + ((lane >> 4) * 16);
    const uint32_t bFragOff = TILE_A
                              + (uint32_t)(wn + (lane & 7) + ((lane >> 4) << 3)) * ROWB
                              + (((lane >> 3) & 1) * 16);

    for (int c = 0; c < NC; ++c) {
        issue(c + 3);
        CP_WAIT3();
        __syncthreads();

        const uint32_t sS = smb + (c & (STAGES-1)) * STAGE_B;
        const uint32_t aBase = sS + aFragOff;
        const uint32_t bBase = sS + bFragOff;

        #pragma unroll
        for (int ks = 0; ks < 2; ++ks) {
            const uint32_t ko = ks * 32;
            uint32_t af[4][4];
            #pragma unroll
            for (int ma = 0; ma < 4; ++ma)
                LDSM_X4(af[ma][0], af[ma][1], af[ma][2], af[ma][3],
                        aBase + ma * (16 * ROWB) + ko);
            uint32_t bf[4][2];
            #pragma unroll
            for (int p = 0; p < 2; ++p) {
                uint32_t r0, r1, r2, r3;
                LDSM_X4(r0, r1, r2, r3, bBase + p * (16 * ROWB) + ko);
                bf[2*p][0] = r0; bf[2*p][1] = r1;
                bf[2*p+1][0] = r2; bf[2*p+1][1] = r3;
            }
            #pragma unroll
            for (int ma = 0; ma < 4; ++ma)
                #pragma unroll
                for (int na = 0; na < 4; ++na)
                    mma16816(acc[ma][na], af[ma], bf[na]);
        }
        __syncthreads();
    }

    // epilogue: bias + relu + store, optional fused row-dot with w2
    const int relu = jb.relu;
    float dot0[4] = {0.f,0.f,0.f,0.f}, dot1[4] = {0.f,0.f,0.f,0.f};
    #pragma unroll
    for (int na = 0; na < 4; ++na) {
        const int col = n0 + wn + na * 8 + (lane & 3) * 2;
        float2 bv = make_float2(0.f, 0.f);
        if (jb.hasbias) bv = *reinterpret_cast<const float2*>(jb.bias + col);
        float2 wv = make_float2(0.f, 0.f);
        if (jb.w2) wv = *reinterpret_cast<const float2*>(jb.w2 + col);
        #pragma unroll
        for (int ma = 0; ma < 4; ++ma) {
            const int row = m0 + wm + ma * 16 + (lane >> 2);
            float2 o0, o1;
            o0.x = acc[ma][na][0] + bv.x; o0.y = acc[ma][na][1] + bv.y;
            o1.x = acc[ma][na][2] + bv.x; o1.y = acc[ma][na][3] + bv.y;
            if (relu) {
                o0.x = fmaxf(o0.x, 0.f); o0.y = fmaxf(o0.y, 0.f);
                o1.x = fmaxf(o1.x, 0.f); o1.y = fmaxf(o1.y, 0.f);
            }
            *reinterpret_cast<float2*>(jb.C + (size_t)row * 512 + col)       = o0;
            *reinterpret_cast<float2*>(jb.C + (size_t)(row + 8) * 512 + col) = o1;
            dot0[ma] += o0.x * wv.x + o0.y * wv.y;
            dot1[ma] += o1.x * wv.x + o1.y * wv.y;
        }
    }

    if (jb.w2) {
        __syncthreads();
        float* sf = reinterpret_cast<float*>(sm);
        #pragma unroll
        for (int ma = 0; ma < 4; ++ma) {
            float v0 = dot0[ma];
            v0 += __shfl_xor_sync(0xffffffffu, v0, 1);
            v0 += __shfl_xor_sync(0xffffffffu, v0, 2);
            float v1 = dot1[ma];
            v1 += __shfl_xor_sync(0xffffffffu, v1, 1);
            v1 += __shfl_xor_sync(0xffffffffu, v1, 2);
            if ((lane & 3) == 0) {
                int lr = wm + ma * 16 + (lane >> 2);       // 0..255
                sf[lr * 4 + (wid & 3)] = v0;
                sf[(lr + 8) * 4 + (wid & 3)] = v1;
            }
        }
        __syncthreads();
        if (tid < 256) {
            float s = sf[tid*4] + sf[tid*4+1] + sf[tid*4+2] + sf[tid*4+3];
            jb.dotp[(size_t)(n0 >> 7) * jb.mrows + m0 + tid] = s;
        }
    }
}

// ---------------- merged LN: sum split-K partials + relu + LN + fp16 split-convert ----------------
__global__ __launch_bounds__(128) void ln_all_k(const float* __restrict__ gt,
                                                const float* __restrict__ bt,
                                                const float* __restrict__ gi,
                                                const float* __restrict__ bi)
{
    const int bx = blockIdx.x, tid = threadIdx.x;
    const float* g; const float* beta; __half* dst;
    int row; bool img;
    if (bx < TROWS) { row = bx;         g = gt; beta = bt; dst = g_AT2 + (size_t)row * LDAD; img = false; }
    else            { row = bx - TROWS; g = gi; beta = bi; dst = g_AI2 + (size_t)row * LDAD; img = true; }

    float4 v;
    if (!img) {
        float4 a = reinterpret_cast<const float4*>(g_T  + (size_t)row * D_)[tid];
        float4 b = reinterpret_cast<const float4*>(g_T2 + (size_t)row * D_)[tid];
        v.x = fmaxf(a.x + b.x, 0.f); v.y = fmaxf(a.y + b.y, 0.f);
        v.z = fmaxf(a.z + b.z, 0.f); v.w = fmaxf(a.w + b.w, 0.f);
    } else {
        float4 a = reinterpret_cast<const float4*>(g_I  + (size_t)row * D_)[tid];
        float4 b = reinterpret_cast<const float4*>(g_I2 + (size_t)row * D_)[tid];
        float4 c = reinterpret_cast<const float4*>(g_I3 + (size_t)row * D_)[tid];
        float4 d = reinterpret_cast<const float4*>(g_I4 + (size_t)row * D_)[tid];
        v.x = fmaxf(a.x + b.x + c.x + d.x, 0.f); v.y = fmaxf(a.y + b.y + c.y + d.y, 0.f);
        v.z = fmaxf(a.z + b.z + c.z + d.z, 0.f); v.w = fmaxf(a.w + b.w + c.w + d.w, 0.f);
    }
    float s  = v.x + v.y + v.z + v.w;
    float ss = v.x * v.x + v.y * v.y + v.z * v.z + v.w * v.w;
    #pragma unroll
    for (int o = 16; o; o >>= 1) {
        s  += __shfl_xor_sync(0xffffffffu, s,  o);
        ss += __shfl_xor_sync(0xffffffffu, ss, o);
    }
    __shared__ float rs[4], rss[4];
    int w = tid >> 5, l = tid & 31;
    if (l == 0) { rs[w] = s; rss[w] = ss; }
    __syncthreads();
    s  = rs[0] + rs[1] + rs[2] + rs[3];
    ss = rss[0] + rss[1] + rss[2] + rss[3];
    float mu   = s * (1.f / D_);
    float var  = ss * (1.f / D_) - mu * mu;
    float rstd = rsqrtf(var + 1e-5f);
    float4 gg = reinterpret_cast<const float4*>(g)[tid];
    float4 bb = reinterpret_cast<const float4*>(beta)[tid];
    v.x = (v.x - mu) * rstd * gg.x + bb.x;
    v.y = (v.y - mu) * rstd * gg.y + bb.y;
    v.z = (v.z - mu) * rstd * gg.z + bb.z;
    v.w = (v.w - mu) * rstd * gg.w + bb.w;
    if (img) reinterpret_cast<float4*>(g_I + (size_t)row * D_)[tid] = v;

    __half h0,h1,h2,h3,l0,l1,l2,l3;
    split_fp16(v.x, h0, l0); split_fp16(v.y, h1, l1);
    split_fp16(v.z, h2, l2); split_fp16(v.w, h3, l3);
    __half2 ph01, ph23, pl01, pl23;
    ph01.x = h0; ph01.y = h1; ph23.x = h2; ph23.y = h3;
    pl01.x = l0; pl01.y = l1; pl23.x = l2; pl23.y = l3;
    __half2* d2 = reinterpret_cast<__half2*>(dst);
    int c2 = tid * 2;
    d2[c2] = ph01;        d2[c2 + 1] = ph23;
    d2[256 + c2] = pl01;  d2[256 + c2 + 1] = pl23;
}

// ---------------- fused pairwise score kernel (packed f32x2) ----------------
static __device__ __forceinline__ unsigned long long f2add(unsigned long long a, unsigned long long b){
    unsigned long long r; asm("add.rn.f32x2 %0, %1, %2;" : "=l"(r) : "l"(a), "l"(b)); return r;
}
static __device__ __forceinline__ unsigned long long f2fma(unsigned long long a, unsigned long long b, unsigned long long c){
    unsigned long long r; asm("fma.rn.f32x2 %0, %1, %2, %3;" : "=l"(r) : "l"(a), "l"(b), "l"(c)); return r;
}
static __device__ __forceinline__ float2 upk2(unsigned long long v){
    float2 f; asm("mov.b64 {%0, %1}, %2;" : "=f"(f.x), "=f"(f.y) : "l"(v)); return f;
}

#define OFF_HI  0
#define OFF_HT  (R_ * SHI_S)
#define OFF_W2  (OFF_HT + 4 * D_)
#define OFF_RED (OFF_W2 + D_)
#define OFF_UR  (OFF_RED + 4 * 160)
#define OFF_TE  (OFF_UR + R_)
#define SCORE_SMEM ((OFF_TE + 4) * 4)

__global__ __launch_bounds__(160) void score_k(const float* __restrict__ W2,
                                               const float* __restrict__ b2p,
                                               float* __restrict__ out)
{
    extern __shared__ float smf[];
    const int b = blockIdx.x, e0 = blockIdx.y * 4;
    const int tid = threadIdx.x;

    {
        const float4* src  = reinterpret_cast<const float4*>(g_HI  + (size_t)b * R_ * D_);
        const float4* src2 = reinterpret_cast<const float4*>(g_HI2 + (size_t)b * R_ * D_);
        for (int i = tid; i < R_ * (D_ / 4); i += 160) {
            int row = i >> 7, c = i & 127;
            float4 a = src[i], d = src2[i];
            float4 o; o.x = a.x + d.x; o.y = a.y + d.y; o.z = a.z + d.z; o.w = a.w + d.w;
            reinterpret_cast<float4*>(smf + OFF_HI + row * SHI_S)[c] = o;
        }
        const float4* srcT  = reinterpret_cast<const float4*>(g_HT  + (size_t)(b * E_ + e0) * D_);
        const float4* srcT2 = reinterpret_cast<const float4*>(g_HT2 + (size_t)(b * E_ + e0) * D_);
        for (int i = tid; i < 4 * (D_ / 4); i += 160) {
            float4 a = srcT[i], d = srcT2[i];
            float4 o; o.x = a.x + d.x; o.y = a.y + d.y; o.z = a.z + d.z; o.w = a.w + d.w;
            reinterpret_cast<float4*>(smf + OFF_HT)[i] = o;
        }
        const float4* srcW = reinterpret_cast<const float4*>(W2);
        for (int i = tid; i < D_ / 4; i += 160)
            reinterpret_cast<float4*>(smf + OFF_W2)[i] = srcW[i];
        if (tid < R_) {
            int r = b * R_ + tid;
            float s = 0.f;
            #pragma unroll
            for (int k = 0; k < 8; ++k) s += g_urp[k * IROWS_P + r];
            smf[OFF_UR + tid] = s;
        }
        if (tid < 4) {
            int r = b * E_ + e0 + tid;
            float s = 0.f;
            #pragma unroll
            for (int k = 0; k < 8; ++k) s += g_tep[k * TROWS + r];
            smf[OFF_TE + tid] = s;
        }
    }
    __syncthreads();

    int q4 = tid / 36;
    int r  = tid - q4 * 36;
    int q  = q4 < 3 ? q4 : 3;

    const ulonglong2* hp = reinterpret_cast<const ulonglong2*>(smf + OFF_HI + r * SHI_S + q * 128);
    const ulonglong2* wp = reinterpret_cast<const ulonglong2*>(smf + OFF_W2 + q * 128);
    const ulonglong2* tp = reinterpret_cast<const ulonglong2*>(smf + OFF_HT + q * 128);

    const unsigned long long ABSM = 0x7FFFFFFF7FFFFFFFull;
    unsigned long long a0 = 0, a1 = 0, a2 = 0, a3 = 0;

    #pragma unroll 8
    for (int j = 0; j < 32; ++j) {
        ulonglong2 h = hp[j];
        ulonglong2 w = wp[j];
        ulonglong2 t;
        t = tp[j];
        a0 = f2fma(f2add(t.x, h.x) & ABSM, w.x, a0);
        a0 = f2fma(f2add(t.y, h.y) & ABSM, w.y, a0);
        t = tp[128 + j];
        a1 = f2fma(f2add(t.x, h.x) & ABSM, w.x, a1);
        a1 = f2fma(f2add(t.y, h.y) & ABSM, w.y, a1);
        t = tp[256 + j];
        a2 = f2fma(f2add(t.x, h.x) & ABSM, w.x, a2);
        a2 = f2fma(f2add(t.y, h.y) & ABSM, w.y, a2);
        t = tp[384 + j];
        a3 = f2fma(f2add(t.x, h.x) & ABSM, w.x, a3);
        a3 = f2fma(f2add(t.y, h.y) & ABSM, w.y, a3);
    }

    float2 p;
    p = upk2(a0); smf[OFF_RED + 0 * 160 + tid] = p.x + p.y;
    p = upk2(a1); smf[OFF_RED + 1 * 160 + tid] = p.x + p.y;
    p = upk2(a2); smf[OFF_RED + 2 * 160 + tid] = p.x + p.y;
    p = upk2(a3); smf[OFF_RED + 3 * 160 + tid] = p.x + p.y;
    __syncthreads();

    if (tid < R_) {
        float b2v = b2p[0];
        float ur  = smf[OFF_UR + tid];
        #pragma unroll
        for (int e = 0; e < 4; ++e) {
            const float* rd = smf + OFF_RED + e * 160;
            float S = rd[tid] + rd[36 + tid] + rd[72 + tid] + rd[108 + tid];
            float raw = 0.5f * (smf[OFF_TE + e] + ur + S) + b2v;
            out[b * (E_ * R_) + (e0 + e) * R_ + tid] = 1.0f / (1.0f + expf(-raw));
        }
    }
}

// ---------------- softmax over E*R per batch + aggregation ----------------
__global__ __launch_bounds__(256) void softagg_k(const float* __restrict__ sc,
                                                 float* __restrict__ out)
{
    __shared__ float s[E_ * R_];
    __shared__ float red[8];
    __shared__ float wr[R_];
    const int b = blockIdx.x, tid = threadIdx.x;
    const int lane = tid & 31, w = tid >> 5;

    float mx = -1e30f;
    for (int i = tid; i < E_ * R_; i += 256) {
        float v = sc[b * E_ * R_ + i];
        s[i] = v;
        mx = fmaxf(mx, v);
    }
    #pragma unroll
    for (int o = 16; o; o >>= 1) mx = fmaxf(mx, __shfl_xor_sync(0xffffffffu, mx, o));
    if (lane == 0) red[w] = mx;
    __syncthreads();
    float m = red[0];
    #pragma unroll
    for (int k = 1; k < 8; ++k) m = fmaxf(m, red[k]);
    __syncthreads();

    float sum = 0.f;
    for (int i = tid; i < E_ * R_; i += 256) {
        float e2 = expf(s[i] - m);
        s[i] = e2;
        sum += e2;
    }
    #pragma unroll
    for (int o = 16; o; o >>= 1) sum += __shfl_xor_sync(0xffffffffu, sum, o);
    if (lane == 0) red[w] = sum;
    __syncthreads();
    float Z = 0.f;
    #pragma unroll
    for (int k = 0; k < 8; ++k) Z += red[k];
    float scale = 1.0f / (Z * (float)E_);

    if (tid < R_) {
        float a = 0.f;
        for (int e = 0; e < E_; ++e) a += s[e * R_ + tid];
        wr[tid] = a * scale;
    }
    __syncthreads();

    for (int d = tid; d < D_; d += 256) {
        float a = 0.f;
        #pragma unroll
        for (int r2 = 0; r2 < R_; ++r2)
            a += wr[r2] * g_I[(size_t)(b * R_ + r2) * D_ + d];
        out[B_ * E_ * R_ + b * D_ + d] = a;
    }
}

// ---------------- launch ----------------
extern "C" void kernel_launch(void* const* d_in, const int* in_sizes, int n_in,
                              void* d_out, int out_size)
{
    (void)in_sizes; (void)n_in; (void)out_size;
    const float* text      = (const float*)d_in[0];
    const float* image     = (const float*)d_in[1];
    const float* W_text    = (const float*)d_in[2];
    const float* b_text    = (const float*)d_in[3];
    const float* g_text    = (const float*)d_in[4];
    const float* beta_text = (const float*)d_in[5];
    const float* W_img     = (const float*)d_in[6];
    const float* b_img     = (const float*)d_in[7];
    const float* g_img     = (const float*)d_in[8];
    const float* beta_img  = (const float*)d_in[9];
    const float* W1        = (const float*)d_in[10];
    const float* b1        = (const float*)d_in[11];
    const float* W2        = (const float*)d_in[12];
    const float* b2        = (const float*)d_in[13];
    float* out = (float*)d_out;

    void* p;
    cudaGetSymbolAddress(&p, g_T);   float* T   = (float*)p;
    cudaGetSymbolAddress(&p, g_T2);  float* T2  = (float*)p;
    cudaGetSymbolAddress(&p, g_I);   float* I   = (float*)p;
    cudaGetSymbolAddress(&p, g_I2);  float* I2  = (float*)p;
    cudaGetSymbolAddress(&p, g_I3);  float* I3  = (float*)p;
    cudaGetSymbolAddress(&p, g_I4);  float* I4  = (float*)p;
    cudaGetSymbolAddress(&p, g_HT);  float* HT  = (float*)p;
    cudaGetSymbolAddress(&p, g_HT2); float* HT2 = (float*)p;
    cudaGetSymbolAddress(&p, g_HI);  float* HI  = (float*)p;
    cudaGetSymbolAddress(&p, g_HI2); float* HI2 = (float*)p;
    cudaGetSymbolAddress(&p, g_tep); float* tep = (float*)p;
    cudaGetSymbolAddress(&p, g_urp); float* urp = (float*)p;
    cudaGetSymbolAddress(&p, g_At);  __half* At  = (__half*)p;
    cudaGetSymbolAddress(&p, g_Ai);  __half* Ai  = (__half*)p;
    cudaGetSymbolAddress(&p, g_AT2); __half* AT2 = (__half*)p;
    cudaGetSymbolAddress(&p, g_AI2); __half* AI2 = (__half*)p;
    cudaGetSymbolAddress(&p, g_Bt);  __half* Bt  = (__half*)p;
    cudaGetSymbolAddress(&p, g_Bi);  __half* Bi  = (__half*)p;
    cudaGetSymbolAddress(&p, g_B1t); __half* B1t = (__half*)p;
    cudaGetSymbolAddress(&p, g_B1i); __half* B1i = (__half*)p;

    cudaFuncSetAttribute(mma_gemm3, cudaFuncAttributeMaxDynamicSharedMemorySize, SM_TOT);
    cudaFuncSetAttribute(score_k,   cudaFuncAttributeMaxDynamicSharedMemorySize, SCORE_SMEM);

    // all conversions in one launch
    conv_all_k<<<1920 + (TROWS*DT_ + IROWS*DI_)/256, 256>>>(W_text, W_img, W1, text, image);

    // phase A: text split-K 2-way + image split-K 4-way (BM=256: text 32 CTAs/split, image 20)
    {
        JobPack P;
        P.j[0] = { At, Bt, b_text,  T,  nullptr, nullptr, LDAT, DT_, 0,    768/32,  TROWS,   0, 1 };
        P.j[1] = { At, Bt, nullptr, T2, nullptr, nullptr, LDAT, DT_, 768,  768/32,  TROWS,   0, 0 };
        P.j[2] = { Ai, Bi, b_img,   I,  nullptr, nullptr, LDAI, DI_, 0,    1024/32, IROWS_P, 0, 1 };
        P.j[3] = { Ai, Bi, nullptr, I2, nullptr, nullptr, LDAI, DI_, 1024, 1024/32, IROWS_P, 0, 0 };
        P.j[4] = { Ai, Bi, nullptr, I3, nullptr, nullptr, LDAI, DI_, 2048, 1024/32, IROWS_P, 0, 0 };
        P.j[5] = { Ai, Bi, nullptr, I4, nullptr, nullptr, LDAI, DI_, 3072, 1024/32, IROWS_P, 0, 0 };
        P.hi[0] = 32; P.hi[1] = 64; P.hi[2] = 84; P.hi[3] = 104; P.hi[4] = 124; P.hi[5] = 144;
        mma_gemm3<<<144, 512, SM_TOT>>>(P);
    }

    // merged LN (sums partials + relu) + fp16 split-convert
    ln_all_k<<<TROWS + IROWS, 128>>>(g_text, beta_text, g_img, beta_img);

    // phase B: split-K 2-way each, fused per-row W2 dot (text 32/split, image 20/split)
    {
        JobPack P;
        P.j[0] = { AT2, B1t, nullptr, HT,  W2, tep,             LDAD, D_, 0,   512/32, TROWS,   0, 0 };
        P.j[1] = { AT2, B1t, nullptr, HT2, W2, tep + 4*TROWS,   LDAD, D_, 512, 512/32, TROWS,   0, 0 };
        P.j[2] = { AI2, B1i, b1,      HI,  W2, urp,             LDAD, D_, 0,   512/32, IROWS_P, 0, 1 };
        P.j[3] = { AI2, B1i, nullptr, HI2, W2, urp + 4*IROWS_P, LDAD, D_, 512, 512/32, IROWS_P, 0, 0 };
        P.j[4] = P.j[3]; P.j[5] = P.j[3];
        P.hi[0] = 32; P.hi[1] = 64; P.hi[2] = 84; P.hi[3] = 104; P.hi[4] = 104; P.hi[5] = 104;
        mma_gemm3<<<104, 512, SM_TOT>>>(P);
    }

    score_k<<<dim3(B_, 16), 160, SCORE_SMEM>>>(W2, b2, out);
    softagg_k<<<B_, 256>>>(out, out);
}

// round 13
// speedup vs baseline: 1.3306x; 1.3306x over previous
#include <cuda_runtime.h>
#include <cuda_fp16.h>
#include <cstdint>
#include <math.h>

// Problem dims
#define B_    32
#define E_    64
#define R_    36
#define D_    512
#define DT_   768
#define DI_   2048
#define TROWS 2048   // B*E
#define IROWS 1152   // B*R
#define IROWS_P 1280 // padded to multiple of 256 for BM=256
#define SHI_S 516

// ---------------- scratch (device globals; .bss zero-initialized) ----------------
__device__ __align__(128) float g_T  [TROWS*D_];
__device__ __align__(128) float g_T2 [TROWS*D_];
__device__ __align__(128) float g_I  [IROWS_P*D_];
__device__ __align__(128) float g_I2 [IROWS_P*D_];
__device__ __align__(128) float g_I3 [IROWS_P*D_];
__device__ __align__(128) float g_I4 [IROWS_P*D_];
__device__ __align__(128) float g_HT [TROWS*D_];
__device__ __align__(128) float g_HT2[TROWS*D_];
__device__ __align__(128) float g_HI [IROWS_P*D_];
__device__ __align__(128) float g_HI2[IROWS_P*D_];
__device__ __align__(128) float g_tep[8*TROWS];
__device__ __align__(128) float g_urp[8*IROWS_P];

__device__ __align__(128) __half g_At [TROWS*DT_];
__device__ __align__(128) __half g_Ai [IROWS_P*DI_];    // rows >=1152 stay zero
__device__ __align__(128) __half g_AT2[TROWS*D_];
__device__ __align__(128) __half g_AI2[IROWS_P*D_];     // rows >=1152 stay zero
__device__ __align__(128) __half g_Bt [D_*DT_];
__device__ __align__(128) __half g_Bi [D_*DI_];
__device__ __align__(128) __half g_B1t[D_*D_];
__device__ __align__(128) __half g_B1i[D_*D_];

// ---------------- helpers ----------------
static __device__ __forceinline__ uint32_t smem_to_u32(const void* p){
    uint32_t a;
    asm("{ .reg .u64 t; cvta.to.shared.u64 t, %1; cvt.u32.u64 %0, t; }" : "=r"(a) : "l"(p));
    return a;
}

#define CP_ASYNC16(smad, gptr) \
    asm volatile("cp.async.ca.shared.global [%0], [%1], 16;" :: "r"(smad), "l"(gptr))
#define CP_COMMIT() asm volatile("cp.async.commit_group;" ::: "memory")
#define CP_WAIT3()  asm volatile("cp.async.wait_group 3;" ::: "memory")

#define LDSM_X4(r0,r1,r2,r3, addr) \
    asm volatile("ldmatrix.sync.aligned.m8n8.x4.shared.b16 {%0,%1,%2,%3}, [%4];" \
        : "=r"(r0), "=r"(r1), "=r"(r2), "=r"(r3) : "r"(addr))

static __device__ __forceinline__ void mma16816(float* c, const uint32_t* a, const uint32_t* b){
    asm volatile(
        "mma.sync.aligned.m16n8k16.row.col.f32.f16.f16.f32 "
        "{%0,%1,%2,%3}, {%4,%5,%6,%7}, {%8,%9}, {%0,%1,%2,%3};"
        : "+f"(c[0]), "+f"(c[1]), "+f"(c[2]), "+f"(c[3])
        : "r"(a[0]), "r"(a[1]), "r"(a[2]), "r"(a[3]), "r"(b[0]), "r"(b[1]));
}

// ---------------- merged conversion kernel (fp16 hi only, both sides) ----------------
__global__ __launch_bounds__(256) void conv_all_k(const float* __restrict__ W_text,
                                                  const float* __restrict__ W_img,
                                                  const float* __restrict__ W1,
                                                  const float* __restrict__ text,
                                                  const float* __restrict__ image)
{
    __shared__ float t[32][33];
    int bx = blockIdx.x;
    if (bx < 1920) {
        const float* src; __half* dst; int K, idx;
        if      (bx < 384)  { src = W_text;       dst = g_Bt;  K = DT_; idx = bx; }
        else if (bx < 1408) { src = W_img;        dst = g_Bi;  K = DI_; idx = bx - 384; }
        else if (bx < 1664) { src = W1;           dst = g_B1t; K = D_;  idx = bx - 1408; }
        else                { src = W1 + D_ * D_; dst = g_B1i; K = D_;  idx = bx - 1664; }
        int kblocks = K / 32;
        int kb = (idx % kblocks) * 32, nb = (idx / kblocks) * 32;
        int tx = threadIdx.x & 31, ty = threadIdx.x >> 5;
        #pragma unroll
        for (int j = 0; j < 4; ++j)
            t[ty + 8*j][tx] = src[(size_t)(kb + ty + 8*j) * 512 + nb + tx];
        __syncthreads();
        #pragma unroll
        for (int j = 0; j < 4; ++j) {
            int n = nb + ty + 8*j, k = kb + tx;
            dst[(size_t)n * K + k] = __float2half_rn(t[tx][ty + 8*j]);
        }
    } else {
        int gi = (bx - 1920) * 256 + threadIdx.x;
        const float* src; __half* dst; int e;
        if (gi < TROWS * DT_) { src = text;  dst = g_At; e = gi; }
        else                  { src = image; dst = g_Ai; e = gi - TROWS * DT_; }
        dst[e] = __float2half_rn(src[e]);
    }
}

// ---------------- mma.sync GEMM: BM=256, BN=128, BK=32, 512 threads, 4-stage cp.async ----------------
struct Job {
    const __half* A;          // [M][lda] fp16 hi
    const __half* B;          // [512][ldb] fp16 hi
    const float* bias;
    float* C;                 // [M][512]
    const float* w2;          // if non-null: fuse per-row dot C.w2 -> dotp
    float* dotp;              // [8][mrows] (split*4 + nblock)
    int lda, ldb;
    int aoff;                 // split-K start (applies to both A and B)
    int NC;                   // chunks of 32
    int mrows;                // dotp row pitch
    int relu, hasbias;
};
struct JobPack { Job j[6]; int hi[6]; };

#define ROWB    80
#define TILE_A  20480          // 256 rows * 80B
#define STAGE_B 30720          // A(256) + B(128) rows
#define STAGES  4
#define SM_TOT  (STAGES*STAGE_B)   // 122880

__global__ __launch_bounds__(512, 1) void mma_gemm3(JobPack P)
{
    extern __shared__ __align__(128) char sm[];
    const uint32_t smb = smem_to_u32(sm);
    const int tid = threadIdx.x;
    const int wid = tid >> 5, lane = tid & 31;

    int bx = (int)blockIdx.x;
    int jx = 0;
    #pragma unroll
    for (int k = 0; k < 5; ++k) jx += (bx >= P.hi[k]);
    Job jb = P.j[jx];
    int rb = bx - (jx ? P.hi[jx-1] : 0);

    const int m0 = (rb >> 2) * 256, n0 = (rb & 3) * 128;
    const int lda = jb.lda, ldb = jb.ldb, NC = jb.NC, aoff = jb.aoff;

    const int wm = (wid >> 2) * 64;   // 0/64/128/192
    const int wn = (wid & 3) * 32;    // 0/32/64/96

    const int cRow = tid >> 2, cCol = tid & 3;   // cRow 0..127

    float acc[4][4][4];
    #pragma unroll
    for (int i = 0; i < 4; ++i)
        #pragma unroll
        for (int j = 0; j < 4; ++j)
            #pragma unroll
            for (int q = 0; q < 4; ++q) acc[i][j][q] = 0.f;

    const __half* gAb  = jb.A + (size_t)(m0 + cRow) * lda + aoff + cCol * 8;
    const __half* gAb2 = jb.A + (size_t)(m0 + cRow + 128) * lda + aoff + cCol * 8;
    const __half* gBb  = jb.B + (size_t)(n0 + cRow) * ldb + aoff + cCol * 8;
    const uint32_t sOffA  = (uint32_t)cRow * ROWB + cCol * 16;
    const uint32_t sOffA2 = (uint32_t)(cRow + 128) * ROWB + cCol * 16;
    const uint32_t sOffB  = TILE_A + (uint32_t)cRow * ROWB + cCol * 16;

    auto issue = [&](int chunk){
        if (chunk < NC) {
            const uint32_t sS = smb + (chunk & (STAGES-1)) * STAGE_B;
            const size_t ko = (size_t)chunk * 32;
            CP_ASYNC16(sS + sOffA,  gAb  + ko);
            CP_ASYNC16(sS + sOffA2, gAb2 + ko);
            CP_ASYNC16(sS + sOffB,  gBb  + ko);
        }
        CP_COMMIT();
    };

    issue(0); issue(1); issue(2);

    const uint32_t aFragOff = (uint32_t)(wm + (lane & 15)) * ROWB + ((lane >> 4) * 16);
    const uint32_t bFragOff = TILE_A
                              + (uint32_t)(wn + (lane & 7) + ((lane >> 4) << 3)) * ROWB
                              + (((lane >> 3) & 1) * 16);

    for (int c = 0; c < NC; ++c) {
        issue(c + 3);
        CP_WAIT3();
        __syncthreads();

        const uint32_t sS = smb + (c & (STAGES-1)) * STAGE_B;
        const uint32_t aBase = sS + aFragOff;
        const uint32_t bBase = sS + bFragOff;

        #pragma unroll
        for (int ks = 0; ks < 2; ++ks) {
            const uint32_t ko = ks * 32;
            uint32_t af[4][4];
            #pragma unroll
            for (int ma = 0; ma < 4; ++ma)
                LDSM_X4(af[ma][0], af[ma][1], af[ma][2], af[ma][3],
                        aBase + ma * (16 * ROWB) + ko);
            uint32_t bf[4][2];
            #pragma unroll
            for (int p = 0; p < 2; ++p) {
                uint32_t r0, r1, r2, r3;
                LDSM_X4(r0, r1, r2, r3, bBase + p * (16 * ROWB) + ko);
                bf[2*p][0] = r0; bf[2*p][1] = r1;
                bf[2*p+1][0] = r2; bf[2*p+1][1] = r3;
            }
            #pragma unroll
            for (int ma = 0; ma < 4; ++ma)
                #pragma unroll
                for (int na = 0; na < 4; ++na)
                    mma16816(acc[ma][na], af[ma], bf[na]);
        }
        __syncthreads();
    }

    // epilogue: bias + relu + store, optional fused row-dot with w2
    const int relu = jb.relu;
    float dot0[4] = {0.f,0.f,0.f,0.f}, dot1[4] = {0.f,0.f,0.f,0.f};
    #pragma unroll
    for (int na = 0; na < 4; ++na) {
        const int col = n0 + wn + na * 8 + (lane & 3) * 2;
        float2 bv = make_float2(0.f, 0.f);
        if (jb.hasbias) bv = *reinterpret_cast<const float2*>(jb.bias + col);
        float2 wv = make_float2(0.f, 0.f);
        if (jb.w2) wv = *reinterpret_cast<const float2*>(jb.w2 + col);
        #pragma unroll
        for (int ma = 0; ma < 4; ++ma) {
            const int row = m0 + wm + ma * 16 + (lane >> 2);
            float2 o0, o1;
            o0.x = acc[ma][na][0] + bv.x; o0.y = acc[ma][na][1] + bv.y;
            o1.x = acc[ma][na][2] + bv.x; o1.y = acc[ma][na][3] + bv.y;
            if (relu) {
                o0.x = fmaxf(o0.x, 0.f); o0.y = fmaxf(o0.y, 0.f);
                o1.x = fmaxf(o1.x, 0.f); o1.y = fmaxf(o1.y, 0.f);
            }
            *reinterpret_cast<float2*>(jb.C + (size_t)row * 512 + col)       = o0;
            *reinterpret_cast<float2*>(jb.C + (size_t)(row + 8) * 512 + col) = o1;
            dot0[ma] += o0.x * wv.x + o0.y * wv.y;
            dot1[ma] += o1.x * wv.x + o1.y * wv.y;
        }
    }

    if (jb.w2) {
        __syncthreads();
        float* sf = reinterpret_cast<float*>(sm);
        #pragma unroll
        for (int ma = 0; ma < 4; ++ma) {
            float v0 = dot0[ma];
            v0 += __shfl_xor_sync(0xffffffffu, v0, 1);
            v0 += __shfl_xor_sync(0xffffffffu, v0, 2);
            float v1 = dot1[ma];
            v1 += __shfl_xor_sync(0xffffffffu, v1, 1);
            v1 += __shfl_xor_sync(0xffffffffu, v1, 2);
            if ((lane & 3) == 0) {
                int lr = wm + ma * 16 + (lane >> 2);       // 0..255
                sf[lr * 4 + (wid & 3)] = v0;
                sf[(lr + 8) * 4 + (wid & 3)] = v1;
            }
        }
        __syncthreads();
        if (tid < 256) {
            float s = sf[tid*4] + sf[tid*4+1] + sf[tid*4+2] + sf[tid*4+3];
            jb.dotp[(size_t)(n0 >> 7) * jb.mrows + m0 + tid] = s;
        }
    }
}

// ---------------- merged LN: sum split-K partials + relu + LN + fp16 convert ----------------
__global__ __launch_bounds__(128) void ln_all_k(const float* __restrict__ gt,
                                                const float* __restrict__ bt,
                                                const float* __restrict__ gi,
                                                const float* __restrict__ bi)
{
    const int bx = blockIdx.x, tid = threadIdx.x;
    const float* g; const float* beta; __half* dst;
    int row; bool img;
    if (bx < TROWS) { row = bx;         g = gt; beta = bt; dst = g_AT2 + (size_t)row * D_; img = false; }
    else            { row = bx - TROWS; g = gi; beta = bi; dst = g_AI2 + (size_t)row * D_; img = true; }

    float4 v;
    if (!img) {
        float4 a = reinterpret_cast<const float4*>(g_T  + (size_t)row * D_)[tid];
        float4 b = reinterpret_cast<const float4*>(g_T2 + (size_t)row * D_)[tid];
        v.x = fmaxf(a.x + b.x, 0.f); v.y = fmaxf(a.y + b.y, 0.f);
        v.z = fmaxf(a.z + b.z, 0.f); v.w = fmaxf(a.w + b.w, 0.f);
    } else {
        float4 a = reinterpret_cast<const float4*>(g_I  + (size_t)row * D_)[tid];
        float4 b = reinterpret_cast<const float4*>(g_I2 + (size_t)row * D_)[tid];
        float4 c = reinterpret_cast<const float4*>(g_I3 + (size_t)row * D_)[tid];
        float4 d = reinterpret_cast<const float4*>(g_I4 + (size_t)row * D_)[tid];
        v.x = fmaxf(a.x + b.x + c.x + d.x, 0.f); v.y = fmaxf(a.y + b.y + c.y + d.y, 0.f);
        v.z = fmaxf(a.z + b.z + c.z + d.z, 0.f); v.w = fmaxf(a.w + b.w + c.w + d.w, 0.f);
    }
    float s  = v.x + v.y + v.z + v.w;
    float ss = v.x * v.x + v.y * v.y + v.z * v.z + v.w * v.w;
    #pragma unroll
    for (int o = 16; o; o >>= 1) {
        s  += __shfl_xor_sync(0xffffffffu, s,  o);
        ss += __shfl_xor_sync(0xffffffffu, ss, o);
    }
    __shared__ float rs[4], rss[4];
    int w = tid >> 5, l = tid & 31;
    if (l == 0) { rs[w] = s; rss[w] = ss; }
    __syncthreads();
    s  = rs[0] + rs[1] + rs[2] + rs[3];
    ss = rss[0] + rss[1] + rss[2] + rss[3];
    float mu   = s * (1.f / D_);
    float var  = ss * (1.f / D_) - mu * mu;
    float rstd = rsqrtf(var + 1e-5f);
    float4 gg = reinterpret_cast<const float4*>(g)[tid];
    float4 bb = reinterpret_cast<const float4*>(beta)[tid];
    v.x = (v.x - mu) * rstd * gg.x + bb.x;
    v.y = (v.y - mu) * rstd * gg.y + bb.y;
    v.z = (v.z - mu) * rstd * gg.z + bb.z;
    v.w = (v.w - mu) * rstd * gg.w + bb.w;
    if (img) reinterpret_cast<float4*>(g_I + (size_t)row * D_)[tid] = v;

    __half2 p01, p23;
    p01.x = __float2half_rn(v.x); p01.y = __float2half_rn(v.y);
    p23.x = __float2half_rn(v.z); p23.y = __float2half_rn(v.w);
    __half2* d2 = reinterpret_cast<__half2*>(dst);
    d2[tid * 2] = p01;
    d2[tid * 2 + 1] = p23;
}

// ---------------- fused pairwise score kernel (packed f32x2) ----------------
static __device__ __forceinline__ unsigned long long f2add(unsigned long long a, unsigned long long b){
    unsigned long long r; asm("add.rn.f32x2 %0, %1, %2;" : "=l"(r) : "l"(a), "l"(b)); return r;
}
static __device__ __forceinline__ unsigned long long f2fma(unsigned long long a, unsigned long long b, unsigned long long c){
    unsigned long long r; asm("fma.rn.f32x2 %0, %1, %2, %3;" : "=l"(r) : "l"(a), "l"(b), "l"(c)); return r;
}
static __device__ __forceinline__ float2 upk2(unsigned long long v){
    float2 f; asm("mov.b64 {%0, %1}, %2;" : "=f"(f.x), "=f"(f.y) : "l"(v)); return f;
}

#define OFF_HI  0
#define OFF_HT  (R_ * SHI_S)
#define OFF_W2  (OFF_HT + 4 * D_)
#define OFF_RED (OFF_W2 + D_)
#define OFF_UR  (OFF_RED + 4 * 160)
#define OFF_TE  (OFF_UR + R_)
#define SCORE_SMEM ((OFF_TE + 4) * 4)

__global__ __launch_bounds__(160) void score_k(const float* __restrict__ W2,
                                               const float* __restrict__ b2p,
                                               float* __restrict__ out)
{
    extern __shared__ float smf[];
    const int b = blockIdx.x, e0 = blockIdx.y * 4;
    const int tid = threadIdx.x;

    {
        const float4* src  = reinterpret_cast<const float4*>(g_HI  + (size_t)b * R_ * D_);
        const float4* src2 = reinterpret_cast<const float4*>(g_HI2 + (size_t)b * R_ * D_);
        for (int i = tid; i < R_ * (D_ / 4); i += 160) {
            int row = i >> 7, c = i & 127;
            float4 a = src[i], d = src2[i];
            float4 o; o.x = a.x + d.x; o.y = a.y + d.y; o.z = a.z + d.z; o.w = a.w + d.w;
            reinterpret_cast<float4*>(smf + OFF_HI + row * SHI_S)[c] = o;
        }
        const float4* srcT  = reinterpret_cast<const float4*>(g_HT  + (size_t)(b * E_ + e0) * D_);
        const float4* srcT2 = reinterpret_cast<const float4*>(g_HT2 + (size_t)(b * E_ + e0) * D_);
        for (int i = tid; i < 4 * (D_ / 4); i += 160) {
            float4 a = srcT[i], d = srcT2[i];
            float4 o; o.x = a.x + d.x; o.y = a.y + d.y; o.z = a.z + d.z; o.w = a.w + d.w;
            reinterpret_cast<float4*>(smf + OFF_HT)[i] = o;
        }
        const float4* srcW = reinterpret_cast<const float4*>(W2);
        for (int i = tid; i < D_ / 4; i += 160)
            reinterpret_cast<float4*>(smf + OFF_W2)[i] = srcW[i];
        if (tid < R_) {
            int r = b * R_ + tid;
            float s = 0.f;
            #pragma unroll
            for (int k = 0; k < 8; ++k) s += g_urp[k * IROWS_P + r];
            smf[OFF_UR + tid] = s;
        }
        if (tid < 4) {
            int r = b * E_ + e0 + tid;
            float s = 0.f;
            #pragma unroll
            for (int k = 0; k < 8; ++k) s += g_tep[k * TROWS + r];
            smf[OFF_TE + tid] = s;
        }
    }
    __syncthreads();

    int q4 = tid / 36;
    int r  = tid - q4 * 36;
    int q  = q4 < 3 ? q4 : 3;

    const ulonglong2* hp = reinterpret_cast<const ulonglong2*>(smf + OFF_HI + r * SHI_S + q * 128);
    const ulonglong2* wp = reinterpret_cast<const ulonglong2*>(smf + OFF_W2 + q * 128);
    const ulonglong2* tp = reinterpret_cast<const ulonglong2*>(smf + OFF_HT + q * 128);

    const unsigned long long ABSM = 0x7FFFFFFF7FFFFFFFull;
    unsigned long long a0 = 0, a1 = 0, a2 = 0, a3 = 0;

    #pragma unroll 8
    for (int j = 0; j < 32; ++j) {
        ulonglong2 h = hp[j];
        ulonglong2 w = wp[j];
        ulonglong2 t;
        t = tp[j];
        a0 = f2fma(f2add(t.x, h.x) & ABSM, w.x, a0);
        a0 = f2fma(f2add(t.y, h.y) & ABSM, w.y, a0);
        t = tp[128 + j];
        a1 = f2fma(f2add(t.x, h.x) & ABSM, w.x, a1);
        a1 = f2fma(f2add(t.y, h.y) & ABSM, w.y, a1);
        t = tp[256 + j];
        a2 = f2fma(f2add(t.x, h.x) & ABSM, w.x, a2);
        a2 = f2fma(f2add(t.y, h.y) & ABSM, w.y, a2);
        t = tp[384 + j];
        a3 = f2fma(f2add(t.x, h.x) & ABSM, w.x, a3);
        a3 = f2fma(f2add(t.y, h.y) & ABSM, w.y, a3);
    }

    float2 p;
    p = upk2(a0); smf[OFF_RED + 0 * 160 + tid] = p.x + p.y;
    p = upk2(a1); smf[OFF_RED + 1 * 160 + tid] = p.x + p.y;
    p = upk2(a2); smf[OFF_RED + 2 * 160 + tid] = p.x + p.y;
    p = upk2(a3); smf[OFF_RED + 3 * 160 + tid] = p.x + p.y;
    __syncthreads();

    if (tid < R_) {
        float b2v = b2p[0];
        float ur  = smf[OFF_UR + tid];
        #pragma unroll
        for (int e = 0; e < 4; ++e) {
            const float* rd = smf + OFF_RED + e * 160;
            float S = rd[tid] + rd[36 + tid] + rd[72 + tid] + rd[108 + tid];
            float raw = 0.5f * (smf[OFF_TE + e] + ur + S) + b2v;
            out[b * (E_ * R_) + (e0 + e) * R_ + tid] = 1.0f / (1.0f + expf(-raw));
        }
    }
}

// ---------------- softmax over E*R per batch + aggregation ----------------
__global__ __launch_bounds__(256) void softagg_k(const float* __restrict__ sc,
                                                 float* __restrict__ out)
{
    __shared__ float s[E_ * R_];
    __shared__ float red[8];
    __shared__ float wr[R_];
    const int b = blockIdx.x, tid = threadIdx.x;
    const int lane = tid & 31, w = tid >> 5;

    float mx = -1e30f;
    for (int i = tid; i < E_ * R_; i += 256) {
        float v = sc[b * E_ * R_ + i];
        s[i] = v;
        mx = fmaxf(mx, v);
    }
    #pragma unroll
    for (int o = 16; o; o >>= 1) mx = fmaxf(mx, __shfl_xor_sync(0xffffffffu, mx, o));
    if (lane == 0) red[w] = mx;
    __syncthreads();
    float m = red[0];
    #pragma unroll
    for (int k = 1; k < 8; ++k) m = fmaxf(m, red[k]);
    __syncthreads();

    float sum = 0.f;
    for (int i = tid; i < E_ * R_; i += 256) {
        float e2 = expf(s[i] - m);
        s[i] = e2;
        sum += e2;
    }
    #pragma unroll
    for (int o = 16; o; o >>= 1) sum += __shfl_xor_sync(0xffffffffu, sum, o);
    if (lane == 0) red[w] = sum;
    __syncthreads();
    float Z = 0.f;
    #pragma unroll
    for (int k = 0; k < 8; ++k) Z += red[k];
    float scale = 1.0f / (Z * (float)E_);

    if (tid < R_) {
        float a = 0.f;
        for (int e = 0; e < E_; ++e) a += s[e * R_ + tid];
        wr[tid] = a * scale;
    }
    __syncthreads();

    for (int d = tid; d < D_; d += 256) {
        float a = 0.f;
        #pragma unroll
        for (int r2 = 0; r2 < R_; ++r2)
            a += wr[r2] * g_I[(size_t)(b * R_ + r2) * D_ + d];
        out[B_ * E_ * R_ + b * D_ + d] = a;
    }
}

// ---------------- launch ----------------
extern "C" void kernel_launch(void* const* d_in, const int* in_sizes, int n_in,
                              void* d_out, int out_size)
{
    (void)in_sizes; (void)n_in; (void)out_size;
    const float* text      = (const float*)d_in[0];
    const float* image     = (const float*)d_in[1];
    const float* W_text    = (const float*)d_in[2];
    const float* b_text    = (const float*)d_in[3];
    const float* g_text    = (const float*)d_in[4];
    const float* beta_text = (const float*)d_in[5];
    const float* W_img     = (const float*)d_in[6];
    const float* b_img     = (const float*)d_in[7];
    const float* g_img     = (const float*)d_in[8];
    const float* beta_img  = (const float*)d_in[9];
    const float* W1        = (const float*)d_in[10];
    const float* b1        = (const float*)d_in[11];
    const float* W2        = (const float*)d_in[12];
    const float* b2        = (const float*)d_in[13];
    float* out = (float*)d_out;

    void* p;
    cudaGetSymbolAddress(&p, g_T);   float* T   = (float*)p;
    cudaGetSymbolAddress(&p, g_T2);  float* T2  = (float*)p;
    cudaGetSymbolAddress(&p, g_I);   float* I   = (float*)p;
    cudaGetSymbolAddress(&p, g_I2);  float* I2  = (float*)p;
    cudaGetSymbolAddress(&p, g_I3);  float* I3  = (float*)p;
    cudaGetSymbolAddress(&p, g_I4);  float* I4  = (float*)p;
    cudaGetSymbolAddress(&p, g_HT);  float* HT  = (float*)p;
    cudaGetSymbolAddress(&p, g_HT2); float* HT2 = (float*)p;
    cudaGetSymbolAddress(&p, g_HI);  float* HI  = (float*)p;
    cudaGetSymbolAddress(&p, g_HI2); float* HI2 = (float*)p;
    cudaGetSymbolAddress(&p, g_tep); float* tep = (float*)p;
    cudaGetSymbolAddress(&p, g_urp); float* urp = (float*)p;
    cudaGetSymbolAddress(&p, g_At);  __half* At  = (__half*)p;
    cudaGetSymbolAddress(&p, g_Ai);  __half* Ai  = (__half*)p;
    cudaGetSymbolAddress(&p, g_AT2); __half* AT2 = (__half*)p;
    cudaGetSymbolAddress(&p, g_AI2); __half* AI2 = (__half*)p;
    cudaGetSymbolAddress(&p, g_Bt);  __half* Bt  = (__half*)p;
    cudaGetSymbolAddress(&p, g_Bi);  __half* Bi  = (__half*)p;
    cudaGetSymbolAddress(&p, g_B1t); __half* B1t = (__half*)p;
    cudaGetSymbolAddress(&p, g_B1i); __half* B1i = (__half*)p;

    cudaFuncSetAttribute(mma_gemm3, cudaFuncAttributeMaxDynamicSharedMemorySize, SM_TOT);
    cudaFuncSetAttribute(score_k,   cudaFuncAttributeMaxDynamicSharedMemorySize, SCORE_SMEM);

    // all conversions in one launch
    conv_all_k<<<1920 + (TROWS*DT_ + IROWS*DI_)/256, 256>>>(W_text, W_img, W1, text, image);

    // phase A: text split-K 2-way (384 each) + image split-K 4-way (512 each)
    {
        JobPack P;
        P.j[0] = { At, Bt, b_text,  T,  nullptr, nullptr, DT_, DT_, 0,    384/32, TROWS,   0, 1 };
        P.j[1] = { At, Bt, nullptr, T2, nullptr, nullptr, DT_, DT_, 384,  384/32, TROWS,   0, 0 };
        P.j[2] = { Ai, Bi, b_img,   I,  nullptr, nullptr, DI_, DI_, 0,    512/32, IROWS_P, 0, 1 };
        P.j[3] = { Ai, Bi, nullptr, I2, nullptr, nullptr, DI_, DI_, 512,  512/32, IROWS_P, 0, 0 };
        P.j[4] = { Ai, Bi, nullptr, I3, nullptr, nullptr, DI_, DI_, 1024, 512/32, IROWS_P, 0, 0 };
        P.j[5] = { Ai, Bi, nullptr, I4, nullptr, nullptr, DI_, DI_, 1536, 512/32, IROWS_P, 0, 0 };
        P.hi[0] = 32; P.hi[1] = 64; P.hi[2] = 84; P.hi[3] = 104; P.hi[4] = 124; P.hi[5] = 144;
        mma_gemm3<<<144, 512, SM_TOT>>>(P);
    }

    // merged LN (sums partials + relu) + fp16 convert
    ln_all_k<<<TROWS + IROWS, 128>>>(g_text, beta_text, g_img, beta_img);

    // phase B: split-K 2-way each (256 each), fused per-row W2 dot
    {
        JobPack P;
        P.j[0] = { AT2, B1t, nullptr, HT,  W2, tep,             D_, D_, 0,   256/32, TROWS,   0, 0 };
        P.j[1] = { AT2, B1t, nullptr, HT2, W2, tep + 4*TROWS,   D_, D_, 256, 256/32, TROWS,   0, 0 };
        P.j[2] = { AI2, B1i, b1,      HI,  W2, urp,             D_, D_, 0,   256/32, IROWS_P, 0, 1 };
        P.j[3] = { AI2, B1i, nullptr, HI2, W2, urp + 4*IROWS_P, D_, D_, 256, 256/32, IROWS_P, 0, 0 };
        P.j[4] = P.j[3]; P.j[5] = P.j[3];
        P.hi[0] = 32; P.hi[1] = 64; P.hi[2] = 84; P.hi[3] = 104; P.hi[4] = 104; P.hi[5] = 104;
        mma_gemm3<<<104, 512, SM_TOT>>>(P);
    }

    score_k<<<dim3(B_, 16), 160, SCORE_SMEM>>>(W2, b2, out);
    softagg_k<<<B_, 256>>>(out, out);
}

// round 14
// speedup vs baseline: 1.5586x; 1.1713x over previous
#include <cuda_runtime.h>
#include <cuda_fp16.h>
#include <cstdint>
#include <math.h>

// Problem dims
#define B_    32
#define E_    64
#define R_    36
#define D_    512
#define DT_   768
#define DI_   2048
#define TROWS 2048   // B*E
#define IROWS 1152   // B*R
#define IROWS_P 1280 // padded to multiple of 256 for BM=256
#define SHI_S 516
#define ET    8      // e-tile in score kernel

// ---------------- scratch (device globals; .bss zero-initialized) ----------------
__device__ __align__(128) float g_T  [TROWS*D_];
__device__ __align__(128) float g_T2 [TROWS*D_];
__device__ __align__(128) float g_I  [IROWS_P*D_];
__device__ __align__(128) float g_I2 [IROWS_P*D_];
__device__ __align__(128) float g_I3 [IROWS_P*D_];
__device__ __align__(128) float g_I4 [IROWS_P*D_];
__device__ __align__(128) float g_HT [TROWS*D_];
__device__ __align__(128) float g_HT2[TROWS*D_];
__device__ __align__(128) float g_HI [IROWS_P*D_];
__device__ __align__(128) float g_HI2[IROWS_P*D_];
__device__ __align__(128) float g_tep[8*TROWS];
__device__ __align__(128) float g_urp[8*IROWS_P];

__device__ __align__(128) __half g_At [TROWS*DT_];
__device__ __align__(128) __half g_Ai [IROWS_P*DI_];    // rows >=1152 stay zero
__device__ __align__(128) __half g_AT2[TROWS*D_];
__device__ __align__(128) __half g_AI2[IROWS_P*D_];     // rows >=1152 stay zero
__device__ __align__(128) __half g_Bt [D_*DT_];
__device__ __align__(128) __half g_Bi [D_*DI_];
__device__ __align__(128) __half g_B1t[D_*D_];
__device__ __align__(128) __half g_B1i[D_*D_];

// ---------------- helpers ----------------
static __device__ __forceinline__ uint32_t smem_to_u32(const void* p){
    uint32_t a;
    asm("{ .reg .u64 t; cvta.to.shared.u64 t, %1; cvt.u32.u64 %0, t; }" : "=r"(a) : "l"(p));
    return a;
}

#define CP_ASYNC16(smad, gptr) \
    asm volatile("cp.async.ca.shared.global [%0], [%1], 16;" :: "r"(smad), "l"(gptr))
#define CP_COMMIT() asm volatile("cp.async.commit_group;" ::: "memory")
#define CP_WAIT3()  asm volatile("cp.async.wait_group 3;" ::: "memory")

#define LDSM_X4(r0,r1,r2,r3, addr) \
    asm volatile("ldmatrix.sync.aligned.m8n8.x4.shared.b16 {%0,%1,%2,%3}, [%4];" \
        : "=r"(r0), "=r"(r1), "=r"(r2), "=r"(r3) : "r"(addr))

static __device__ __forceinline__ void mma16816(float* c, const uint32_t* a, const uint32_t* b){
    asm volatile(
        "mma.sync.aligned.m16n8k16.row.col.f32.f16.f16.f32 "
        "{%0,%1,%2,%3}, {%4,%5,%6,%7}, {%8,%9}, {%0,%1,%2,%3};"
        : "+f"(c[0]), "+f"(c[1]), "+f"(c[2]), "+f"(c[3])
        : "r"(a[0]), "r"(a[1]), "r"(a[2]), "r"(a[3]), "r"(b[0]), "r"(b[1]));
}

// ---------------- merged conversion kernel (vectorized) ----------------
// blocks [0,1920): weight transpose  [K,512] fp32 -> [512][K] fp16 (32x32 tiles)
// blocks [1920,5760): A-side convert [M,K] fp32 -> [M,K] fp16, 4 elems/thread
__global__ __launch_bounds__(256) void conv_all_k(const float* __restrict__ W_text,
                                                  const float* __restrict__ W_img,
                                                  const float* __restrict__ W1,
                                                  const float* __restrict__ text,
                                                  const float* __restrict__ image)
{
    __shared__ float t[32][33];
    int bx = blockIdx.x;
    int tid = threadIdx.x;
    if (bx < 1920) {
        const float* src; __half* dst; int K, idx;
        if      (bx < 384)  { src = W_text;       dst = g_Bt;  K = DT_; idx = bx; }
        else if (bx < 1408) { src = W_img;        dst = g_Bi;  K = DI_; idx = bx - 384; }
        else if (bx < 1664) { src = W1;           dst = g_B1t; K = D_;  idx = bx - 1408; }
        else                { src = W1 + D_ * D_; dst = g_B1i; K = D_;  idx = bx - 1664; }
        int kblocks = K / 32;
        int kb = (idx % kblocks) * 32, nb = (idx / kblocks) * 32;
        int tx = tid & 31, ty = tid >> 5;
        #pragma unroll
        for (int j = 0; j < 4; ++j)
            t[ty + 8*j][tx] = src[(size_t)(kb + ty + 8*j) * 512 + nb + tx];
        __syncthreads();
        // each thread writes 4 contiguous k of one n-row
        int n  = nb + (tid >> 3);
        int k4 = (tid & 7) * 4;
        __half2 p0, p1;
        p0.x = __float2half_rn(t[k4 + 0][tid >> 3]);
        p0.y = __float2half_rn(t[k4 + 1][tid >> 3]);
        p1.x = __float2half_rn(t[k4 + 2][tid >> 3]);
        p1.y = __float2half_rn(t[k4 + 3][tid >> 3]);
        __half2* d2 = reinterpret_cast<__half2*>(dst + (size_t)n * K + kb + k4);
        d2[0] = p0; d2[1] = p1;
    } else {
        int gi = (bx - 1920) * 256 + tid;               // float4 index
        const int TQ = TROWS * DT_ / 4;                 // 393216
        const float4* src; __half* dst; int e4;
        if (gi < TQ) { src = reinterpret_cast<const float4*>(text);  dst = g_At; e4 = gi; }
        else         { src = reinterpret_cast<const float4*>(image); dst = g_Ai; e4 = gi - TQ; }
        float4 v = src[e4];
        __half2 p0, p1;
        p0.x = __float2half_rn(v.x); p0.y = __float2half_rn(v.y);
        p1.x = __float2half_rn(v.z); p1.y = __float2half_rn(v.w);
        __half2* d2 = reinterpret_cast<__half2*>(dst + (size_t)e4 * 4);
        d2[0] = p0; d2[1] = p1;
    }
}

// ---------------- mma.sync GEMM: BM=256, BN=128, BK=32, 512 threads, 4-stage cp.async ----------------
struct Job {
    const __half* A;          // [M][lda] fp16 hi
    const __half* B;          // [512][ldb] fp16 hi
    const float* bias;
    float* C;                 // [M][512]
    const float* w2;          // if non-null: fuse per-row dot C.w2 -> dotp
    float* dotp;              // [8][mrows] (split*4 + nblock)
    int lda, ldb;
    int aoff;                 // split-K start (applies to both A and B)
    int NC;                   // chunks of 32
    int mrows;                // dotp row pitch
    int relu, hasbias;
};
struct JobPack { Job j[6]; int hi[6]; };

#define ROWB    80
#define TILE_A  20480          // 256 rows * 80B
#define STAGE_B 30720          // A(256) + B(128) rows
#define STAGES  4
#define SM_TOT  (STAGES*STAGE_B)   // 122880

__global__ __launch_bounds__(512, 1) void mma_gemm3(JobPack P)
{
    extern __shared__ __align__(128) char sm[];
    const uint32_t smb = smem_to_u32(sm);
    const int tid = threadIdx.x;
    const int wid = tid >> 5, lane = tid & 31;

    int bx = (int)blockIdx.x;
    int jx = 0;
    #pragma unroll
    for (int k = 0; k < 5; ++k) jx += (bx >= P.hi[k]);
    Job jb = P.j[jx];
    int rb = bx - (jx ? P.hi[jx-1] : 0);

    const int m0 = (rb >> 2) * 256, n0 = (rb & 3) * 128;
    const int lda = jb.lda, ldb = jb.ldb, NC = jb.NC, aoff = jb.aoff;

    const int wm = (wid >> 2) * 64;   // 0/64/128/192
    const int wn = (wid & 3) * 32;    // 0/32/64/96

    const int cRow = tid >> 2, cCol = tid & 3;   // cRow 0..127

    float acc[4][4][4];
    #pragma unroll
    for (int i = 0; i < 4; ++i)
        #pragma unroll
        for (int j = 0; j < 4; ++j)
            #pragma unroll
            for (int q = 0; q < 4; ++q) acc[i][j][q] = 0.f;

    const __half* gAb  = jb.A + (size_t)(m0 + cRow) * lda + aoff + cCol * 8;
    const __half* gAb2 = jb.A + (size_t)(m0 + cRow + 128) * lda + aoff + cCol * 8;
    const __half* gBb  = jb.B + (size_t)(n0 + cRow) * ldb + aoff + cCol * 8;
    const uint32_t sOffA  = (uint32_t)cRow * ROWB + cCol * 16;
    const uint32_t sOffA2 = (uint32_t)(cRow + 128) * ROWB + cCol * 16;
    const uint32_t sOffB  = TILE_A + (uint32_t)cRow * ROWB + cCol * 16;

    auto issue = [&](int chunk){
        if (chunk < NC) {
            const uint32_t sS = smb + (chunk & (STAGES-1)) * STAGE_B;
            const size_t ko = (size_t)chunk * 32;
            CP_ASYNC16(sS + sOffA,  gAb  + ko);
            CP_ASYNC16(sS + sOffA2, gAb2 + ko);
            CP_ASYNC16(sS + sOffB,  gBb  + ko);
        }
        CP_COMMIT();
    };

    issue(0); issue(1); issue(2);

    const uint32_t aFragOff = (uint32_t)(wm + (lane & 15)) * ROWB + ((lane >> 4) * 16);
    const uint32_t bFragOff = TILE_A
                              + (uint32_t)(wn + (lane & 7) + ((lane >> 4) << 3)) * ROWB
                              + (((lane >> 3) & 1) * 16);

    for (int c = 0; c < NC; ++c) {
        issue(c + 3);
        CP_WAIT3();
        __syncthreads();

        const uint32_t sS = smb + (c & (STAGES-1)) * STAGE_B;
        const uint32_t aBase = sS + aFragOff;
        const uint32_t bBase = sS + bFragOff;

        #pragma unroll
        for (int ks = 0; ks < 2; ++ks) {
            const uint32_t ko = ks * 32;
            uint32_t af[4][4];
            #pragma unroll
            for (int ma = 0; ma < 4; ++ma)
                LDSM_X4(af[ma][0], af[ma][1], af[ma][2], af[ma][3],
                        aBase + ma * (16 * ROWB) + ko);
            uint32_t bf[4][2];
            #pragma unroll
            for (int p = 0; p < 2; ++p) {
                uint32_t r0, r1, r2, r3;
                LDSM_X4(r0, r1, r2, r3, bBase + p * (16 * ROWB) + ko);
                bf[2*p][0] = r0; bf[2*p][1] = r1;
                bf[2*p+1][0] = r2; bf[2*p+1][1] = r3;
            }
            #pragma unroll
            for (int ma = 0; ma < 4; ++ma)
                #pragma unroll
                for (int na = 0; na < 4; ++na)
                    mma16816(acc[ma][na], af[ma], bf[na]);
        }
        __syncthreads();
    }

    // epilogue: bias + relu + store, optional fused row-dot with w2
    const int relu = jb.relu;
    float dot0[4] = {0.f,0.f,0.f,0.f}, dot1[4] = {0.f,0.f,0.f,0.f};
    #pragma unroll
    for (int na = 0; na < 4; ++na) {
        const int col = n0 + wn + na * 8 + (lane & 3) * 2;
        float2 bv = make_float2(0.f, 0.f);
        if (jb.hasbias) bv = *reinterpret_cast<const float2*>(jb.bias + col);
        float2 wv = make_float2(0.f, 0.f);
        if (jb.w2) wv = *reinterpret_cast<const float2*>(jb.w2 + col);
        #pragma unroll
        for (int ma = 0; ma < 4; ++ma) {
            const int row = m0 + wm + ma * 16 + (lane >> 2);
            float2 o0, o1;
            o0.x = acc[ma][na][0] + bv.x; o0.y = acc[ma][na][1] + bv.y;
            o1.x = acc[ma][na][2] + bv.x; o1.y = acc[ma][na][3] + bv.y;
            if (relu) {
                o0.x = fmaxf(o0.x, 0.f); o0.y = fmaxf(o0.y, 0.f);
                o1.x = fmaxf(o1.x, 0.f); o1.y = fmaxf(o1.y, 0.f);
            }
            *reinterpret_cast<float2*>(jb.C + (size_t)row * 512 + col)       = o0;
            *reinterpret_cast<float2*>(jb.C + (size_t)(row + 8) * 512 + col) = o1;
            dot0[ma] += o0.x * wv.x + o0.y * wv.y;
            dot1[ma] += o1.x * wv.x + o1.y * wv.y;
        }
    }

    if (jb.w2) {
        __syncthreads();
        float* sf = reinterpret_cast<float*>(sm);
        #pragma unroll
        for (int ma = 0; ma < 4; ++ma) {
            float v0 = dot0[ma];
            v0 += __shfl_xor_sync(0xffffffffu, v0, 1);
            v0 += __shfl_xor_sync(0xffffffffu, v0, 2);
            float v1 = dot1[ma];
            v1 += __shfl_xor_sync(0xffffffffu, v1, 1);
            v1 += __shfl_xor_sync(0xffffffffu, v1, 2);
            if ((lane & 3) == 0) {
                int lr = wm + ma * 16 + (lane >> 2);       // 0..255
                sf[lr * 4 + (wid & 3)] = v0;
                sf[(lr + 8) * 4 + (wid & 3)] = v1;
            }
        }
        __syncthreads();
        if (tid < 256) {
            float s = sf[tid*4] + sf[tid*4+1] + sf[tid*4+2] + sf[tid*4+3];
            jb.dotp[(size_t)(n0 >> 7) * jb.mrows + m0 + tid] = s;
        }
    }
}

// ---------------- merged LN: sum split-K partials + relu + LN + fp16 convert ----------------
__global__ __launch_bounds__(128) void ln_all_k(const float* __restrict__ gt,
                                                const float* __restrict__ bt,
                                                const float* __restrict__ gi,
                                                const float* __restrict__ bi)
{
    const int bx = blockIdx.x, tid = threadIdx.x;
    const float* g; const float* beta; __half* dst;
    int row; bool img;
    if (bx < TROWS) { row = bx;         g = gt; beta = bt; dst = g_AT2 + (size_t)row * D_; img = false; }
    else            { row = bx - TROWS; g = gi; beta = bi; dst = g_AI2 + (size_t)row * D_; img = true; }

    float4 v;
    if (!img) {
        float4 a = reinterpret_cast<const float4*>(g_T  + (size_t)row * D_)[tid];
        float4 b = reinterpret_cast<const float4*>(g_T2 + (size_t)row * D_)[tid];
        v.x = fmaxf(a.x + b.x, 0.f); v.y = fmaxf(a.y + b.y, 0.f);
        v.z = fmaxf(a.z + b.z, 0.f); v.w = fmaxf(a.w + b.w, 0.f);
    } else {
        float4 a = reinterpret_cast<const float4*>(g_I  + (size_t)row * D_)[tid];
        float4 b = reinterpret_cast<const float4*>(g_I2 + (size_t)row * D_)[tid];
        float4 c = reinterpret_cast<const float4*>(g_I3 + (size_t)row * D_)[tid];
        float4 d = reinterpret_cast<const float4*>(g_I4 + (size_t)row * D_)[tid];
        v.x = fmaxf(a.x + b.x + c.x + d.x, 0.f); v.y = fmaxf(a.y + b.y + c.y + d.y, 0.f);
        v.z = fmaxf(a.z + b.z + c.z + d.z, 0.f); v.w = fmaxf(a.w + b.w + c.w + d.w, 0.f);
    }
    float s  = v.x + v.y + v.z + v.w;
    float ss = v.x * v.x + v.y * v.y + v.z * v.z + v.w * v.w;
    #pragma unroll
    for (int o = 16; o; o >>= 1) {
        s  += __shfl_xor_sync(0xffffffffu, s,  o);
        ss += __shfl_xor_sync(0xffffffffu, ss, o);
    }
    __shared__ float rs[4], rss[4];
    int w = tid >> 5, l = tid & 31;
    if (l == 0) { rs[w] = s; rss[w] = ss; }
    __syncthreads();
    s  = rs[0] + rs[1] + rs[2] + rs[3];
    ss = rss[0] + rss[1] + rss[2] + rss[3];
    float mu   = s * (1.f / D_);
    float var  = ss * (1.f / D_) - mu * mu;
    float rstd = rsqrtf(var + 1e-5f);
    float4 gg = reinterpret_cast<const float4*>(g)[tid];
    float4 bb = reinterpret_cast<const float4*>(beta)[tid];
    v.x = (v.x - mu) * rstd * gg.x + bb.x;
    v.y = (v.y - mu) * rstd * gg.y + bb.y;
    v.z = (v.z - mu) * rstd * gg.z + bb.z;
    v.w = (v.w - mu) * rstd * gg.w + bb.w;
    if (img) reinterpret_cast<float4*>(g_I + (size_t)row * D_)[tid] = v;

    __half2 p01, p23;
    p01.x = __float2half_rn(v.x); p01.y = __float2half_rn(v.y);
    p23.x = __float2half_rn(v.z); p23.y = __float2half_rn(v.w);
    __half2* d2 = reinterpret_cast<__half2*>(dst);
    d2[tid * 2] = p01;
    d2[tid * 2 + 1] = p23;
}

// ---------------- fused pairwise score kernel (packed f32x2), e-tile = 8 ----------------
static __device__ __forceinline__ unsigned long long f2add(unsigned long long a, unsigned long long b){
    unsigned long long r; asm("add.rn.f32x2 %0, %1, %2;" : "=l"(r) : "l"(a), "l"(b)); return r;
}
static __device__ __forceinline__ unsigned long long f2fma(unsigned long long a, unsigned long long b, unsigned long long c){
    unsigned long long r; asm("fma.rn.f32x2 %0, %1, %2, %3;" : "=l"(r) : "l"(a), "l"(b), "l"(c)); return r;
}
static __device__ __forceinline__ float2 upk2(unsigned long long v){
    float2 f; asm("mov.b64 {%0, %1}, %2;" : "=f"(f.x), "=f"(f.y) : "l"(v)); return f;
}

#define OFF_HI  0
#define OFF_HT  (R_ * SHI_S)                  // 18576
#define OFF_W2  (OFF_HT + ET * D_)            // 22672
#define OFF_RED (OFF_W2 + D_)                 // 23184
#define OFF_UR  (OFF_RED + ET * 160)          // 24464
#define OFF_TE  (OFF_UR + R_)                 // 24500
#define SCORE_SMEM ((OFF_TE + ET) * 4)        // 98032 bytes

__global__ __launch_bounds__(160) void score_k(const float* __restrict__ W2,
                                               const float* __restrict__ b2p,
                                               float* __restrict__ out)
{
    extern __shared__ float smf[];
    const int b = blockIdx.x, e0 = blockIdx.y * ET;
    const int tid = threadIdx.x;

    {
        const float4* src  = reinterpret_cast<const float4*>(g_HI  + (size_t)b * R_ * D_);
        const float4* src2 = reinterpret_cast<const float4*>(g_HI2 + (size_t)b * R_ * D_);
        for (int i = tid; i < R_ * (D_ / 4); i += 160) {
            int row = i >> 7, c = i & 127;
            float4 a = src[i], d = src2[i];
            float4 o; o.x = a.x + d.x; o.y = a.y + d.y; o.z = a.z + d.z; o.w = a.w + d.w;
            reinterpret_cast<float4*>(smf + OFF_HI + row * SHI_S)[c] = o;
        }
        const float4* srcT  = reinterpret_cast<const float4*>(g_HT  + (size_t)(b * E_ + e0) * D_);
        const float4* srcT2 = reinterpret_cast<const float4*>(g_HT2 + (size_t)(b * E_ + e0) * D_);
        for (int i = tid; i < ET * (D_ / 4); i += 160) {
            float4 a = srcT[i], d = srcT2[i];
            float4 o; o.x = a.x + d.x; o.y = a.y + d.y; o.z = a.z + d.z; o.w = a.w + d.w;
            reinterpret_cast<float4*>(smf + OFF_HT)[i] = o;
        }
        const float4* srcW = reinterpret_cast<const float4*>(W2);
        for (int i = tid; i < D_ / 4; i += 160)
            reinterpret_cast<float4*>(smf + OFF_W2)[i] = srcW[i];
        if (tid < R_) {
            int r = b * R_ + tid;
            float s = 0.f;
            #pragma unroll
            for (int k = 0; k < 8; ++k) s += g_urp[k * IROWS_P + r];
            smf[OFF_UR + tid] = s;
        }
        if (tid < ET) {
            int r = b * E_ + e0 + tid;
            float s = 0.f;
            #pragma unroll
            for (int k = 0; k < 8; ++k) s += g_tep[k * TROWS + r];
            smf[OFF_TE + tid] = s;
        }
    }
    __syncthreads();

    int q4 = tid / 36;
    int r  = tid - q4 * 36;
    int q  = q4 < 3 ? q4 : 3;

    const ulonglong2* hp = reinterpret_cast<const ulonglong2*>(smf + OFF_HI + r * SHI_S + q * 128);
    const ulonglong2* wp = reinterpret_cast<const ulonglong2*>(smf + OFF_W2 + q * 128);
    const ulonglong2* tp = reinterpret_cast<const ulonglong2*>(smf + OFF_HT + q * 128);

    const unsigned long long ABSM = 0x7FFFFFFF7FFFFFFFull;
    unsigned long long ac[ET];
    #pragma unroll
    for (int e = 0; e < ET; ++e) ac[e] = 0;

    #pragma unroll 4
    for (int j = 0; j < 32; ++j) {
        ulonglong2 h = hp[j];
        ulonglong2 w = wp[j];
        #pragma unroll
        for (int e = 0; e < ET; ++e) {
            ulonglong2 t = tp[e * 128 + j];
            ac[e] = f2fma(f2add(t.x, h.x) & ABSM, w.x, ac[e]);
            ac[e] = f2fma(f2add(t.y, h.y) & ABSM, w.y, ac[e]);
        }
    }

    #pragma unroll
    for (int e = 0; e < ET; ++e) {
        float2 p = upk2(ac[e]);
        smf[OFF_RED + e * 160 + tid] = p.x + p.y;
    }
    __syncthreads();

    if (tid < R_) {
        float b2v = b2p[0];
        float ur  = smf[OFF_UR + tid];
        #pragma unroll
        for (int e = 0; e < ET; ++e) {
            const float* rd = smf + OFF_RED + e * 160;
            float S = rd[tid] + rd[36 + tid] + rd[72 + tid] + rd[108 + tid];
            float raw = 0.5f * (smf[OFF_TE + e] + ur + S) + b2v;
            out[b * (E_ * R_) + (e0 + e) * R_ + tid] = 1.0f / (1.0f + expf(-raw));
        }
    }
}

// ---------------- softmax over E*R per batch + aggregation ----------------
__global__ __launch_bounds__(256) void softagg_k(const float* __restrict__ sc,
                                                 float* __restrict__ out)
{
    __shared__ float s[E_ * R_];
    __shared__ float red[8];
    __shared__ float wr[R_];
    const int b = blockIdx.x, tid = threadIdx.x;
    const int lane = tid & 31, w = tid >> 5;

    float mx = -1e30f;
    for (int i = tid; i < E_ * R_; i += 256) {
        float v = sc[b * E_ * R_ + i];
        s[i] = v;
        mx = fmaxf(mx, v);
    }
    #pragma unroll
    for (int o = 16; o; o >>= 1) mx = fmaxf(mx, __shfl_xor_sync(0xffffffffu, mx, o));
    if (lane == 0) red[w] = mx;
    __syncthreads();
    float m = red[0];
    #pragma unroll
    for (int k = 1; k < 8; ++k) m = fmaxf(m, red[k]);
    __syncthreads();

    float sum = 0.f;
    for (int i = tid; i < E_ * R_; i += 256) {
        float e2 = expf(s[i] - m);
        s[i] = e2;
        sum += e2;
    }
    #pragma unroll
    for (int o = 16; o; o >>= 1) sum += __shfl_xor_sync(0xffffffffu, sum, o);
    if (lane == 0) red[w] = sum;
    __syncthreads();
    float Z = 0.f;
    #pragma unroll
    for (int k = 0; k < 8; ++k) Z += red[k];
    float scale = 1.0f / (Z * (float)E_);

    if (tid < R_) {
        float a = 0.f;
        for (int e = 0; e < E_; ++e) a += s[e * R_ + tid];
        wr[tid] = a * scale;
    }
    __syncthreads();

    for (int d = tid; d < D_; d += 256) {
        float a = 0.f;
        #pragma unroll
        for (int r2 = 0; r2 < R_; ++r2)
            a += wr[r2] * g_I[(size_t)(b * R_ + r2) * D_ + d];
        out[B_ * E_ * R_ + b * D_ + d] = a;
    }
}

// ---------------- launch ----------------
extern "C" void kernel_launch(void* const* d_in, const int* in_sizes, int n_in,
                              void* d_out, int out_size)
{
    (void)in_sizes; (void)n_in; (void)out_size;
    const float* text      = (const float*)d_in[0];
    const float* image     = (const float*)d_in[1];
    const float* W_text    = (const float*)d_in[2];
    const float* b_text    = (const float*)d_in[3];
    const float* g_text    = (const float*)d_in[4];
    const float* beta_text = (const float*)d_in[5];
    const float* W_img     = (const float*)d_in[6];
    const float* b_img     = (const float*)d_in[7];
    const float* g_img     = (const float*)d_in[8];
    const float* beta_img  = (const float*)d_in[9];
    const float* W1        = (const float*)d_in[10];
    const float* b1        = (const float*)d_in[11];
    const float* W2        = (const float*)d_in[12];
    const float* b2        = (const float*)d_in[13];
    float* out = (float*)d_out;

    void* p;
    cudaGetSymbolAddress(&p, g_T);   float* T   = (float*)p;
    cudaGetSymbolAddress(&p, g_T2);  float* T2  = (float*)p;
    cudaGetSymbolAddress(&p, g_I);   float* I   = (float*)p;
    cudaGetSymbolAddress(&p, g_I2);  float* I2  = (float*)p;
    cudaGetSymbolAddress(&p, g_I3);  float* I3  = (float*)p;
    cudaGetSymbolAddress(&p, g_I4);  float* I4  = (float*)p;
    cudaGetSymbolAddress(&p, g_HT);  float* HT  = (float*)p;
    cudaGetSymbolAddress(&p, g_HT2); float* HT2 = (float*)p;
    cudaGetSymbolAddress(&p, g_HI);  float* HI  = (float*)p;
    cudaGetSymbolAddress(&p, g_HI2); float* HI2 = (float*)p;
    cudaGetSymbolAddress(&p, g_tep); float* tep = (float*)p;
    cudaGetSymbolAddress(&p, g_urp); float* urp = (float*)p;
    cudaGetSymbolAddress(&p, g_At);  __half* At  = (__half*)p;
    cudaGetSymbolAddress(&p, g_Ai);  __half* Ai  = (__half*)p;
    cudaGetSymbolAddress(&p, g_AT2); __half* AT2 = (__half*)p;
    cudaGetSymbolAddress(&p, g_AI2); __half* AI2 = (__half*)p;
    cudaGetSymbolAddress(&p, g_Bt);  __half* Bt  = (__half*)p;
    cudaGetSymbolAddress(&p, g_Bi);  __half* Bi  = (__half*)p;
    cudaGetSymbolAddress(&p, g_B1t); __half* B1t = (__half*)p;
    cudaGetSymbolAddress(&p, g_B1i); __half* B1i = (__half*)p;

    cudaFuncSetAttribute(mma_gemm3, cudaFuncAttributeMaxDynamicSharedMemorySize, SM_TOT);
    cudaFuncSetAttribute(score_k,   cudaFuncAttributeMaxDynamicSharedMemorySize, SCORE_SMEM);

    // all conversions in one launch (vectorized A-side)
    conv_all_k<<<1920 + (TROWS*DT_ + IROWS*DI_)/1024, 256>>>(W_text, W_img, W1, text, image);

    // phase A: text split-K 2-way (384 each) + image split-K 4-way (512 each)
    {
        JobPack P;
        P.j[0] = { At, Bt, b_text,  T,  nullptr, nullptr, DT_, DT_, 0,    384/32, TROWS,   0, 1 };
        P.j[1] = { At, Bt, nullptr, T2, nullptr, nullptr, DT_, DT_, 384,  384/32, TROWS,   0, 0 };
        P.j[2] = { Ai, Bi, b_img,   I,  nullptr, nullptr, DI_, DI_, 0,    512/32, IROWS_P, 0, 1 };
        P.j[3] = { Ai, Bi, nullptr, I2, nullptr, nullptr, DI_, DI_, 512,  512/32, IROWS_P, 0, 0 };
        P.j[4] = { Ai, Bi, nullptr, I3, nullptr, nullptr, DI_, DI_, 1024, 512/32, IROWS_P, 0, 0 };
        P.j[5] = { Ai, Bi, nullptr, I4, nullptr, nullptr, DI_, DI_, 1536, 512/32, IROWS_P, 0, 0 };
        P.hi[0] = 32; P.hi[1] = 64; P.hi[2] = 84; P.hi[3] = 104; P.hi[4] = 124; P.hi[5] = 144;
        mma_gemm3<<<144, 512, SM_TOT>>>(P);
    }

    // merged LN (sums partials + relu) + fp16 convert
    ln_all_k<<<TROWS + IROWS, 128>>>(g_text, beta_text, g_img, beta_img);

    // phase B: split-K 2-way each (256 each), fused per-row W2 dot
    {
        JobPack P;
        P.j[0] = { AT2, B1t, nullptr, HT,  W2, tep,             D_, D_, 0,   256/32, TROWS,   0, 0 };
        P.j[1] = { AT2, B1t, nullptr, HT2, W2, tep + 4*TROWS,   D_, D_, 256, 256/32, TROWS,   0, 0 };
        P.j[2] = { AI2, B1i, b1,      HI,  W2, urp,             D_, D_, 0,   256/32, IROWS_P, 0, 1 };
        P.j[3] = { AI2, B1i, nullptr, HI2, W2, urp + 4*IROWS_P, D_, D_, 256, 256/32, IROWS_P, 0, 0 };
        P.j[4] = P.j[3]; P.j[5] = P.j[3];
        P.hi[0] = 32; P.hi[1] = 64; P.hi[2] = 84; P.hi[3] = 104; P.hi[4] = 104; P.hi[5] = 104;
        mma_gemm3<<<104, 512, SM_TOT>>>(P);
    }

    score_k<<<dim3(B_, E_/ET), 160, SCORE_SMEM>>>(W2, b2, out);
    softagg_k<<<B_, 256>>>(out, out);
}

// round 15
// speedup vs baseline: 1.5945x; 1.0230x over previous
#include <cuda_runtime.h>
#include <cuda_fp16.h>
#include <cstdint>
#include <math.h>

// Problem dims
#define B_    32
#define E_    64
#define R_    36
#define D_    512
#define DT_   768
#define DI_   2048
#define TROWS 2048   // B*E
#define IROWS 1152   // B*R
#define IROWS_P 1280 // padded to multiple of 256 for BM=256
#define SHI_S 516
#define ET    8      // e-tile in score kernel
#define STH   320    // score kernel threads

// ---------------- scratch (device globals; .bss zero-initialized) ----------------
__device__ __align__(128) float g_T  [TROWS*D_];
__device__ __align__(128) float g_T2 [TROWS*D_];
__device__ __align__(128) float g_I  [IROWS_P*D_];
__device__ __align__(128) float g_I2 [IROWS_P*D_];
__device__ __align__(128) float g_I3 [IROWS_P*D_];
__device__ __align__(128) float g_I4 [IROWS_P*D_];
__device__ __align__(128) float g_HT [TROWS*D_];
__device__ __align__(128) float g_HT2[TROWS*D_];
__device__ __align__(128) float g_HI [IROWS_P*D_];
__device__ __align__(128) float g_HI2[IROWS_P*D_];
__device__ __align__(128) float g_tep[8*TROWS];
__device__ __align__(128) float g_urp[8*IROWS_P];
__device__ int g_cnt[B_];   // per-batch ticket; self-resetting

__device__ __align__(128) __half g_At [TROWS*DT_];
__device__ __align__(128) __half g_Ai [IROWS_P*DI_];    // rows >=1152 stay zero
__device__ __align__(128) __half g_AT2[TROWS*D_];
__device__ __align__(128) __half g_AI2[IROWS_P*D_];     // rows >=1152 stay zero
__device__ __align__(128) __half g_Bt [D_*DT_];
__device__ __align__(128) __half g_Bi [D_*DI_];
__device__ __align__(128) __half g_B1t[D_*D_];
__device__ __align__(128) __half g_B1i[D_*D_];

// ---------------- helpers ----------------
static __device__ __forceinline__ uint32_t smem_to_u32(const void* p){
    uint32_t a;
    asm("{ .reg .u64 t; cvta.to.shared.u64 t, %1; cvt.u32.u64 %0, t; }" : "=r"(a) : "l"(p));
    return a;
}

#define CP_ASYNC16(smad, gptr) \
    asm volatile("cp.async.ca.shared.global [%0], [%1], 16;" :: "r"(smad), "l"(gptr))
#define CP_COMMIT() asm volatile("cp.async.commit_group;" ::: "memory")
#define CP_WAIT3()  asm volatile("cp.async.wait_group 3;" ::: "memory")

#define LDSM_X4(r0,r1,r2,r3, addr) \
    asm volatile("ldmatrix.sync.aligned.m8n8.x4.shared.b16 {%0,%1,%2,%3}, [%4];" \
        : "=r"(r0), "=r"(r1), "=r"(r2), "=r"(r3) : "r"(addr))

static __device__ __forceinline__ void mma16816(float* c, const uint32_t* a, const uint32_t* b){
    asm volatile(
        "mma.sync.aligned.m16n8k16.row.col.f32.f16.f16.f32 "
        "{%0,%1,%2,%3}, {%4,%5,%6,%7}, {%8,%9}, {%0,%1,%2,%3};"
        : "+f"(c[0]), "+f"(c[1]), "+f"(c[2]), "+f"(c[3])
        : "r"(a[0]), "r"(a[1]), "r"(a[2]), "r"(a[3]), "r"(b[0]), "r"(b[1]));
}

// ---------------- merged conversion kernel (vectorized) ----------------
__global__ __launch_bounds__(256) void conv_all_k(const float* __restrict__ W_text,
                                                  const float* __restrict__ W_img,
                                                  const float* __restrict__ W1,
                                                  const float* __restrict__ text,
                                                  const float* __restrict__ image)
{
    __shared__ float t[32][33];
    int bx = blockIdx.x;
    int tid = threadIdx.x;
    if (bx < 1920) {
        const float* src; __half* dst; int K, idx;
        if      (bx < 384)  { src = W_text;       dst = g_Bt;  K = DT_; idx = bx; }
        else if (bx < 1408) { src = W_img;        dst = g_Bi;  K = DI_; idx = bx - 384; }
        else if (bx < 1664) { src = W1;           dst = g_B1t; K = D_;  idx = bx - 1408; }
        else                { src = W1 + D_ * D_; dst = g_B1i; K = D_;  idx = bx - 1664; }
        int kblocks = K / 32;
        int kb = (idx % kblocks) * 32, nb = (idx / kblocks) * 32;
        int tx = tid & 31, ty = tid >> 5;
        #pragma unroll
        for (int j = 0; j < 4; ++j)
            t[ty + 8*j][tx] = src[(size_t)(kb + ty + 8*j) * 512 + nb + tx];
        __syncthreads();
        int n  = nb + (tid >> 3);
        int k4 = (tid & 7) * 4;
        __half2 p0, p1;
        p0.x = __float2half_rn(t[k4 + 0][tid >> 3]);
        p0.y = __float2half_rn(t[k4 + 1][tid >> 3]);
        p1.x = __float2half_rn(t[k4 + 2][tid >> 3]);
        p1.y = __float2half_rn(t[k4 + 3][tid >> 3]);
        __half2* d2 = reinterpret_cast<__half2*>(dst + (size_t)n * K + kb + k4);
        d2[0] = p0; d2[1] = p1;
    } else {
        int gi = (bx - 1920) * 256 + tid;               // float4 index
        const int TQ = TROWS * DT_ / 4;
        const float4* src; __half* dst; int e4;
        if (gi < TQ) { src = reinterpret_cast<const float4*>(text);  dst = g_At; e4 = gi; }
        else         { src = reinterpret_cast<const float4*>(image); dst = g_Ai; e4 = gi - TQ; }
        float4 v = src[e4];
        __half2 p0, p1;
        p0.x = __float2half_rn(v.x); p0.y = __float2half_rn(v.y);
        p1.x = __float2half_rn(v.z); p1.y = __float2half_rn(v.w);
        __half2* d2 = reinterpret_cast<__half2*>(dst + (size_t)e4 * 4);
        d2[0] = p0; d2[1] = p1;
    }
}

// ---------------- mma.sync GEMM: BM=256, BN=128, BK=32, 512 threads, 4-stage cp.async ----------------
struct Job {
    const __half* A;
    const __half* B;
    const float* bias;
    float* C;
    const float* w2;
    float* dotp;
    int lda, ldb;
    int aoff;
    int NC;
    int mrows;
    int relu, hasbias;
};
struct JobPack { Job j[6]; int hi[6]; };

#define ROWB    80
#define TILE_A  20480
#define STAGE_B 30720
#define STAGES  4
#define SM_TOT  (STAGES*STAGE_B)   // 122880

__global__ __launch_bounds__(512, 1) void mma_gemm3(JobPack P)
{
    extern __shared__ __align__(128) char sm[];
    const uint32_t smb = smem_to_u32(sm);
    const int tid = threadIdx.x;
    const int wid = tid >> 5, lane = tid & 31;

    int bx = (int)blockIdx.x;
    int jx = 0;
    #pragma unroll
    for (int k = 0; k < 5; ++k) jx += (bx >= P.hi[k]);
    Job jb = P.j[jx];
    int rb = bx - (jx ? P.hi[jx-1] : 0);

    const int m0 = (rb >> 2) * 256, n0 = (rb & 3) * 128;
    const int lda = jb.lda, ldb = jb.ldb, NC = jb.NC, aoff = jb.aoff;

    const int wm = (wid >> 2) * 64;
    const int wn = (wid & 3) * 32;

    const int cRow = tid >> 2, cCol = tid & 3;

    float acc[4][4][4];
    #pragma unroll
    for (int i = 0; i < 4; ++i)
        #pragma unroll
        for (int j = 0; j < 4; ++j)
            #pragma unroll
            for (int q = 0; q < 4; ++q) acc[i][j][q] = 0.f;

    const __half* gAb  = jb.A + (size_t)(m0 + cRow) * lda + aoff + cCol * 8;
    const __half* gAb2 = jb.A + (size_t)(m0 + cRow + 128) * lda + aoff + cCol * 8;
    const __half* gBb  = jb.B + (size_t)(n0 + cRow) * ldb + aoff + cCol * 8;
    const uint32_t sOffA  = (uint32_t)cRow * ROWB + cCol * 16;
    const uint32_t sOffA2 = (uint32_t)(cRow + 128) * ROWB + cCol * 16;
    const uint32_t sOffB  = TILE_A + (uint32_t)cRow * ROWB + cCol * 16;

    auto issue = [&](int chunk){
        if (chunk < NC) {
            const uint32_t sS = smb + (chunk & (STAGES-1)) * STAGE_B;
            const size_t ko = (size_t)chunk * 32;
            CP_ASYNC16(sS + sOffA,  gAb  + ko);
            CP_ASYNC16(sS + sOffA2, gAb2 + ko);
            CP_ASYNC16(sS + sOffB,  gBb  + ko);
        }
        CP_COMMIT();
    };

    issue(0); issue(1); issue(2);

    const uint32_t aFragOff = (uint32_t)(wm + (lane & 15)) * ROWB + ((lane >> 4) * 16);
    const uint32_t bFragOff = TILE_A
                              + (uint32_t)(wn + (lane & 7) + ((lane >> 4) << 3)) * ROWB
                              + (((lane >> 3) & 1) * 16);

    for (int c = 0; c < NC; ++c) {
        issue(c + 3);
        CP_WAIT3();
        __syncthreads();

        const uint32_t sS = smb + (c & (STAGES-1)) * STAGE_B;
        const uint32_t aBase = sS + aFragOff;
        const uint32_t bBase = sS + bFragOff;

        #pragma unroll
        for (int ks = 0; ks < 2; ++ks) {
            const uint32_t ko = ks * 32;
            uint32_t af[4][4];
            #pragma unroll
            for (int ma = 0; ma < 4; ++ma)
                LDSM_X4(af[ma][0], af[ma][1], af[ma][2], af[ma][3],
                        aBase + ma * (16 * ROWB) + ko);
            uint32_t bf[4][2];
            #pragma unroll
            for (int p = 0; p < 2; ++p) {
                uint32_t r0, r1, r2, r3;
                LDSM_X4(r0, r1, r2, r3, bBase + p * (16 * ROWB) + ko);
                bf[2*p][0] = r0; bf[2*p][1] = r1;
                bf[2*p+1][0] = r2; bf[2*p+1][1] = r3;
            }
            #pragma unroll
            for (int ma = 0; ma < 4; ++ma)
                #pragma unroll
                for (int na = 0; na < 4; ++na)
                    mma16816(acc[ma][na], af[ma], bf[na]);
        }
        __syncthreads();
    }

    const int relu = jb.relu;
    float dot0[4] = {0.f,0.f,0.f,0.f}, dot1[4] = {0.f,0.f,0.f,0.f};
    #pragma unroll
    for (int na = 0; na < 4; ++na) {
        const int col = n0 + wn + na * 8 + (lane & 3) * 2;
        float2 bv = make_float2(0.f, 0.f);
        if (jb.hasbias) bv = *reinterpret_cast<const float2*>(jb.bias + col);
        float2 wv = make_float2(0.f, 0.f);
        if (jb.w2) wv = *reinterpret_cast<const float2*>(jb.w2 + col);
        #pragma unroll
        for (int ma = 0; ma < 4; ++ma) {
            const int row = m0 + wm + ma * 16 + (lane >> 2);
            float2 o0, o1;
            o0.x = acc[ma][na][0] + bv.x; o0.y = acc[ma][na][1] + bv.y;
            o1.x = acc[ma][na][2] + bv.x; o1.y = acc[ma][na][3] + bv.y;
            if (relu) {
                o0.x = fmaxf(o0.x, 0.f); o0.y = fmaxf(o0.y, 0.f);
                o1.x = fmaxf(o1.x, 0.f); o1.y = fmaxf(o1.y, 0.f);
            }
            *reinterpret_cast<float2*>(jb.C + (size_t)row * 512 + col)       = o0;
            *reinterpret_cast<float2*>(jb.C + (size_t)(row + 8) * 512 + col) = o1;
            dot0[ma] += o0.x * wv.x + o0.y * wv.y;
            dot1[ma] += o1.x * wv.x + o1.y * wv.y;
        }
    }

    if (jb.w2) {
        __syncthreads();
        float* sf = reinterpret_cast<float*>(sm);
        #pragma unroll
        for (int ma = 0; ma < 4; ++ma) {
            float v0 = dot0[ma];
            v0 += __shfl_xor_sync(0xffffffffu, v0, 1);
            v0 += __shfl_xor_sync(0xffffffffu, v0, 2);
            float v1 = dot1[ma];
            v1 += __shfl_xor_sync(0xffffffffu, v1, 1);
            v1 += __shfl_xor_sync(0xffffffffu, v1, 2);
            if ((lane & 3) == 0) {
                int lr = wm + ma * 16 + (lane >> 2);
                sf[lr * 4 + (wid & 3)] = v0;
                sf[(lr + 8) * 4 + (wid & 3)] = v1;
            }
        }
        __syncthreads();
        if (tid < 256) {
            float s = sf[tid*4] + sf[tid*4+1] + sf[tid*4+2] + sf[tid*4+3];
            jb.dotp[(size_t)(n0 >> 7) * jb.mrows + m0 + tid] = s;
        }
    }
}

// ---------------- merged LN: sum split-K partials + relu + LN + fp16 convert ----------------
__global__ __launch_bounds__(128) void ln_all_k(const float* __restrict__ gt,
                                                const float* __restrict__ bt,
                                                const float* __restrict__ gi,
                                                const float* __restrict__ bi)
{
    const int bx = blockIdx.x, tid = threadIdx.x;
    const float* g; const float* beta; __half* dst;
    int row; bool img;
    if (bx < TROWS) { row = bx;         g = gt; beta = bt; dst = g_AT2 + (size_t)row * D_; img = false; }
    else            { row = bx - TROWS; g = gi; beta = bi; dst = g_AI2 + (size_t)row * D_; img = true; }

    float4 v;
    if (!img) {
        float4 a = reinterpret_cast<const float4*>(g_T  + (size_t)row * D_)[tid];
        float4 b = reinterpret_cast<const float4*>(g_T2 + (size_t)row * D_)[tid];
        v.x = fmaxf(a.x + b.x, 0.f); v.y = fmaxf(a.y + b.y, 0.f);
        v.z = fmaxf(a.z + b.z, 0.f); v.w = fmaxf(a.w + b.w, 0.f);
    } else {
        float4 a = reinterpret_cast<const float4*>(g_I  + (size_t)row * D_)[tid];
        float4 b = reinterpret_cast<const float4*>(g_I2 + (size_t)row * D_)[tid];
        float4 c = reinterpret_cast<const float4*>(g_I3 + (size_t)row * D_)[tid];
        float4 d = reinterpret_cast<const float4*>(g_I4 + (size_t)row * D_)[tid];
        v.x = fmaxf(a.x + b.x + c.x + d.x, 0.f); v.y = fmaxf(a.y + b.y + c.y + d.y, 0.f);
        v.z = fmaxf(a.z + b.z + c.z + d.z, 0.f); v.w = fmaxf(a.w + b.w + c.w + d.w, 0.f);
    }
    float s  = v.x + v.y + v.z + v.w;
    float ss = v.x * v.x + v.y * v.y + v.z * v.z + v.w * v.w;
    #pragma unroll
    for (int o = 16; o; o >>= 1) {
        s  += __shfl_xor_sync(0xffffffffu, s,  o);
        ss += __shfl_xor_sync(0xffffffffu, ss, o);
    }
    __shared__ float rs[4], rss[4];
    int w = tid >> 5, l = tid & 31;
    if (l == 0) { rs[w] = s; rss[w] = ss; }
    __syncthreads();
    s  = rs[0] + rs[1] + rs[2] + rs[3];
    ss = rss[0] + rss[1] + rss[2] + rss[3];
    float mu   = s * (1.f / D_);
    float var  = ss * (1.f / D_) - mu * mu;
    float rstd = rsqrtf(var + 1e-5f);
    float4 gg = reinterpret_cast<const float4*>(g)[tid];
    float4 bb = reinterpret_cast<const float4*>(beta)[tid];
    v.x = (v.x - mu) * rstd * gg.x + bb.x;
    v.y = (v.y - mu) * rstd * gg.y + bb.y;
    v.z = (v.z - mu) * rstd * gg.z + bb.z;
    v.w = (v.w - mu) * rstd * gg.w + bb.w;
    if (img) reinterpret_cast<float4*>(g_I + (size_t)row * D_)[tid] = v;

    __half2 p01, p23;
    p01.x = __float2half_rn(v.x); p01.y = __float2half_rn(v.y);
    p23.x = __float2half_rn(v.z); p23.y = __float2half_rn(v.w);
    __half2* d2 = reinterpret_cast<__half2*>(dst);
    d2[tid * 2] = p01;
    d2[tid * 2 + 1] = p23;
}

// ---------------- fused score + last-block softmax/agg ----------------
static __device__ __forceinline__ unsigned long long f2add(unsigned long long a, unsigned long long b){
    unsigned long long r; asm("add.rn.f32x2 %0, %1, %2;" : "=l"(r) : "l"(a), "l"(b)); return r;
}
static __device__ __forceinline__ unsigned long long f2fma(unsigned long long a, unsigned long long b, unsigned long long c){
    unsigned long long r; asm("fma.rn.f32x2 %0, %1, %2, %3;" : "=l"(r) : "l"(a), "l"(b), "l"(c)); return r;
}
static __device__ __forceinline__ float2 upk2(unsigned long long v){
    float2 f; asm("mov.b64 {%0, %1}, %2;" : "=f"(f.x), "=f"(f.y) : "l"(v)); return f;
}

#define OFF_HI  0
#define OFF_HT  (R_ * SHI_S)                  // 18576
#define OFF_W2  (OFF_HT + ET * D_)            // 22672
#define OFF_RED (OFF_W2 + D_)                 // 23184
#define OFF_UR  (OFF_RED + ET * STH)          // 25744
#define OFF_TE  (OFF_UR + R_)                 // 25780
#define SCORE_SMEM ((OFF_TE + ET) * 4)        // 103152 bytes

__global__ __launch_bounds__(STH) void score_k(const float* __restrict__ W2,
                                               const float* __restrict__ b2p,
                                               float* __restrict__ out)
{
    extern __shared__ float smf[];
    const int b = blockIdx.x, e0 = blockIdx.y * ET;
    const int tid = threadIdx.x;

    {
        const float4* src  = reinterpret_cast<const float4*>(g_HI  + (size_t)b * R_ * D_);
        const float4* src2 = reinterpret_cast<const float4*>(g_HI2 + (size_t)b * R_ * D_);
        for (int i = tid; i < R_ * (D_ / 4); i += STH) {
            int row = i >> 7, c = i & 127;
            float4 a = src[i], d = src2[i];
            float4 o; o.x = a.x + d.x; o.y = a.y + d.y; o.z = a.z + d.z; o.w = a.w + d.w;
            reinterpret_cast<float4*>(smf + OFF_HI + row * SHI_S)[c] = o;
        }
        const float4* srcT  = reinterpret_cast<const float4*>(g_HT  + (size_t)(b * E_ + e0) * D_);
        const float4* srcT2 = reinterpret_cast<const float4*>(g_HT2 + (size_t)(b * E_ + e0) * D_);
        for (int i = tid; i < ET * (D_ / 4); i += STH) {
            float4 a = srcT[i], d = srcT2[i];
            float4 o; o.x = a.x + d.x; o.y = a.y + d.y; o.z = a.z + d.z; o.w = a.w + d.w;
            reinterpret_cast<float4*>(smf + OFF_HT)[i] = o;
        }
        const float4* srcW = reinterpret_cast<const float4*>(W2);
        for (int i = tid; i < D_ / 4; i += STH)
            reinterpret_cast<float4*>(smf + OFF_W2)[i] = srcW[i];
        if (tid < R_) {
            int r = b * R_ + tid;
            float s = 0.f;
            #pragma unroll
            for (int k = 0; k < 8; ++k) s += g_urp[k * IROWS_P + r];
            smf[OFF_UR + tid] = s;
        }
        if (tid < ET) {
            int r = b * E_ + e0 + tid;
            float s = 0.f;
            #pragma unroll
            for (int k = 0; k < 8; ++k) s += g_tep[k * TROWS + r];
            smf[OFF_TE + tid] = s;
        }
    }
    __syncthreads();

    // 8 d-slices of 64 x 36 r
    int q8 = tid / 36;
    int r  = tid - q8 * 36;
    int q  = q8 < 7 ? q8 : 7;
    if (q8 > 7) r = tid - 8 * 36;    // spare threads duplicate slice 7 (results unread)

    const ulonglong2* hp = reinterpret_cast<const ulonglong2*>(smf + OFF_HI + r * SHI_S + q * 64);
    const ulonglong2* wp = reinterpret_cast<const ulonglong2*>(smf + OFF_W2 + q * 64);
    const ulonglong2* tp = reinterpret_cast<const ulonglong2*>(smf + OFF_HT + q * 64);

    const unsigned long long ABSM = 0x7FFFFFFF7FFFFFFFull;
    unsigned long long ac[ET];
    #pragma unroll
    for (int e = 0; e < ET; ++e) ac[e] = 0;

    #pragma unroll 4
    for (int j = 0; j < 16; ++j) {
        ulonglong2 h = hp[j];
        ulonglong2 w = wp[j];
        #pragma unroll
        for (int e = 0; e < ET; ++e) {
            ulonglong2 t = tp[e * 128 + j];
            ac[e] = f2fma(f2add(t.x, h.x) & ABSM, w.x, ac[e]);
            ac[e] = f2fma(f2add(t.y, h.y) & ABSM, w.y, ac[e]);
        }
    }

    #pragma unroll
    for (int e = 0; e < ET; ++e) {
        float2 p = upk2(ac[e]);
        smf[OFF_RED + e * STH + tid] = p.x + p.y;
    }
    __syncthreads();

    if (tid < R_) {
        float b2v = b2p[0];
        float ur  = smf[OFF_UR + tid];
        #pragma unroll
        for (int e = 0; e < ET; ++e) {
            const float* rd = smf + OFF_RED + e * STH;
            float S = 0.f;
            #pragma unroll
            for (int k = 0; k < 8; ++k) S += rd[k * 36 + tid];
            float raw = 0.5f * (smf[OFF_TE + e] + ur + S) + b2v;
            out[b * (E_ * R_) + (e0 + e) * R_ + tid] = 1.0f / (1.0f + expf(-raw));
        }
    }

    // ------- last-block ticket: do softmax + aggregation for this batch -------
    __threadfence();
    __shared__ int ticket;
    __syncthreads();
    if (tid == 0) ticket = atomicAdd(&g_cnt[b], 1);
    __syncthreads();
    if (ticket != (E_ / ET) - 1) return;
    if (tid == 0) g_cnt[b] = 0;     // self-reset for next graph replay

    float* s   = smf;               // reuse smem: 2304 scores
    float* red = smf + E_ * R_;     // 10 warp partials
    float* wr  = red + 16;          // 36 weights
    const int lane = tid & 31, w = tid >> 5;

    float mx = -1e30f;
    for (int i = tid; i < E_ * R_; i += STH) {
        float v = out[b * E_ * R_ + i];
        s[i] = v;
        mx = fmaxf(mx, v);
    }
    #pragma unroll
    for (int o = 16; o; o >>= 1) mx = fmaxf(mx, __shfl_xor_sync(0xffffffffu, mx, o));
    if (lane == 0) red[w] = mx;
    __syncthreads();
    float m = red[0];
    #pragma unroll
    for (int k = 1; k < 10; ++k) m = fmaxf(m, red[k]);
    __syncthreads();

    float sum = 0.f;
    for (int i = tid; i < E_ * R_; i += STH) {
        float e2 = expf(s[i] - m);
        s[i] = e2;
        sum += e2;
    }
    #pragma unroll
    for (int o = 16; o; o >>= 1) sum += __shfl_xor_sync(0xffffffffu, sum, o);
    if (lane == 0) red[w] = sum;
    __syncthreads();
    float Z = 0.f;
    #pragma unroll
    for (int k = 0; k < 10; ++k) Z += red[k];
    float scale = 1.0f / (Z * (float)E_);

    if (tid < R_) {
        float a = 0.f;
        for (int e = 0; e < E_; ++e) a += s[e * R_ + tid];
        wr[tid] = a * scale;
    }
    __syncthreads();

    for (int d = tid; d < D_; d += STH) {
        float a = 0.f;
        #pragma unroll
        for (int r2 = 0; r2 < R_; ++r2)
            a += wr[r2] * g_I[(size_t)(b * R_ + r2) * D_ + d];
        out[B_ * E_ * R_ + b * D_ + d] = a;
    }
}

// ---------------- launch ----------------
extern "C" void kernel_launch(void* const* d_in, const int* in_sizes, int n_in,
                              void* d_out, int out_size)
{
    (void)in_sizes; (void)n_in; (void)out_size;
    const float* text      = (const float*)d_in[0];
    const float* image     = (const float*)d_in[1];
    const float* W_text    = (const float*)d_in[2];
    const float* b_text    = (const float*)d_in[3];
    const float* g_text    = (const float*)d_in[4];
    const float* beta_text = (const float*)d_in[5];
    const float* W_img     = (const float*)d_in[6];
    const float* b_img     = (const float*)d_in[7];
    const float* g_img     = (const float*)d_in[8];
    const float* beta_img  = (const float*)d_in[9];
    const float* W1        = (const float*)d_in[10];
    const float* b1        = (const float*)d_in[11];
    const float* W2        = (const float*)d_in[12];
    const float* b2        = (const float*)d_in[13];
    float* out = (float*)d_out;

    void* p;
    cudaGetSymbolAddress(&p, g_T);   float* T   = (float*)p;
    cudaGetSymbolAddress(&p, g_T2);  float* T2  = (float*)p;
    cudaGetSymbolAddress(&p, g_I);   float* I   = (float*)p;
    cudaGetSymbolAddress(&p, g_I2);  float* I2  = (float*)p;
    cudaGetSymbolAddress(&p, g_I3);  float* I3  = (float*)p;
    cudaGetSymbolAddress(&p, g_I4);  float* I4  = (float*)p;
    cudaGetSymbolAddress(&p, g_HT);  float* HT  = (float*)p;
    cudaGetSymbolAddress(&p, g_HT2); float* HT2 = (float*)p;
    cudaGetSymbolAddress(&p, g_HI);  float* HI  = (float*)p;
    cudaGetSymbolAddress(&p, g_HI2); float* HI2 = (float*)p;
    cudaGetSymbolAddress(&p, g_tep); float* tep = (float*)p;
    cudaGetSymbolAddress(&p, g_urp); float* urp = (float*)p;
    cudaGetSymbolAddress(&p, g_At);  __half* At  = (__half*)p;
    cudaGetSymbolAddress(&p, g_Ai);  __half* Ai  = (__half*)p;
    cudaGetSymbolAddress(&p, g_AT2); __half* AT2 = (__half*)p;
    cudaGetSymbolAddress(&p, g_AI2); __half* AI2 = (__half*)p;
    cudaGetSymbolAddress(&p, g_Bt);  __half* Bt  = (__half*)p;
    cudaGetSymbolAddress(&p, g_Bi);  __half* Bi  = (__half*)p;
    cudaGetSymbolAddress(&p, g_B1t); __half* B1t = (__half*)p;
    cudaGetSymbolAddress(&p, g_B1i); __half* B1i = (__half*)p;

    cudaFuncSetAttribute(mma_gemm3, cudaFuncAttributeMaxDynamicSharedMemorySize, SM_TOT);
    cudaFuncSetAttribute(score_k,   cudaFuncAttributeMaxDynamicSharedMemorySize, SCORE_SMEM);

    // all conversions in one launch (vectorized A-side)
    conv_all_k<<<1920 + (TROWS*DT_ + IROWS*DI_)/1024, 256>>>(W_text, W_img, W1, text, image);

    // phase A: text split-K 2-way (384 each) + image split-K 4-way (512 each)
    {
        JobPack P;
        P.j[0] = { At, Bt, b_text,  T,  nullptr, nullptr, DT_, DT_, 0,    384/32, TROWS,   0, 1 };
        P.j[1] = { At, Bt, nullptr, T2, nullptr, nullptr, DT_, DT_, 384,  384/32, TROWS,   0, 0 };
        P.j[2] = { Ai, Bi, b_img,   I,  nullptr, nullptr, DI_, DI_, 0,    512/32, IROWS_P, 0, 1 };
        P.j[3] = { Ai, Bi, nullptr, I2, nullptr, nullptr, DI_, DI_, 512,  512/32, IROWS_P, 0, 0 };
        P.j[4] = { Ai, Bi, nullptr, I3, nullptr, nullptr, DI_, DI_, 1024, 512/32, IROWS_P, 0, 0 };
        P.j[5] = { Ai, Bi, nullptr, I4, nullptr, nullptr, DI_, DI_, 1536, 512/32, IROWS_P, 0, 0 };
        P.hi[0] = 32; P.hi[1] = 64; P.hi[2] = 84; P.hi[3] = 104; P.hi[4] = 124; P.hi[5] = 144;
        mma_gemm3<<<144, 512, SM_TOT>>>(P);
    }

    // merged LN (sums partials + relu) + fp16 convert
    ln_all_k<<<TROWS + IROWS, 128>>>(g_text, beta_text, g_img, beta_img);

    // phase B: split-K 2-way each (256 each), fused per-row W2 dot
    {
        JobPack P;
        P.j[0] = { AT2, B1t, nullptr, HT,  W2, tep,             D_, D_, 0,   256/32, TROWS,   0, 0 };
        P.j[1] = { AT2, B1t, nullptr, HT2, W2, tep + 4*TROWS,   D_, D_, 256, 256/32, TROWS,   0, 0 };
        P.j[2] = { AI2, B1i, b1,      HI,  W2, urp,             D_, D_, 0,   256/32, IROWS_P, 0, 1 };
        P.j[3] = { AI2, B1i, nullptr, HI2, W2, urp + 4*IROWS_P, D_, D_, 256, 256/32, IROWS_P, 0, 0 };
        P.j[4] = P.j[3]; P.j[5] = P.j[3];
        P.hi[0] = 32; P.hi[1] = 64; P.hi[2] = 84; P.hi[3] = 104; P.hi[4] = 104; P.hi[5] = 104;
        mma_gemm3<<<104, 512, SM_TOT>>>(P);
    }

    // fused score + per-batch softmax/aggregation (last-block ticket)
    score_k<<<dim3(B_, E_/ET), STH, SCORE_SMEM>>>(W2, b2, out);
}